// round 7
// baseline (speedup 1.0000x reference)
#include <cuda_runtime.h>
#include <cuda_fp16.h>
#include <math.h>

#define N_NODES 50000
#define DEG     16
#define WIDTH   256
#define BATCH   8192
#define EPS     1e-12f
#define NREF    (BATCH * DEG)             // 131072 neighbor consumer refs
#define SCANB   ((N_NODES + 1023) / 1024) // 49
#define AGGB_BYTES (BATCH * WIDTH * 2)    // 4,194,304 = d_out region1 size

#define LDA 40     // A staging tile leading dim (halves): 80B rows, ldmatrix conflict-free
#define LDB 264    // B staging tile leading dim (halves): 528B rows
#define LDH 264    // H1/nm2 smem leading dim (halves)

// ---- device globals: ~0.93MB TOTAL (big scratch lives in d_out) ----
__device__ int      g_owner[N_NODES];     // last batch writer (-1 none)
__device__ int      g_roff [N_NODES + 1]; // reverse-adjacency offsets
__device__ int      g_rlist[NREF];        // consumer batch-row ids
__device__ int      g_bsum [64];
__device__ int      g_boff [64];
__device__ unsigned g_barCount;           // manual grid barrier (self-resetting)
__device__ unsigned g_barPhase;

// ---------------------------------------------------------------------------
// mma helpers
// ---------------------------------------------------------------------------
__device__ __forceinline__ unsigned smem_u32(const void* p) {
    return (unsigned)__cvta_generic_to_shared(p);
}
__device__ __forceinline__ void ldm_x4(unsigned& r0, unsigned& r1, unsigned& r2,
                                       unsigned& r3, unsigned a) {
    asm volatile("ldmatrix.sync.aligned.m8n8.x4.shared.b16 {%0,%1,%2,%3},[%4];"
                 : "=r"(r0), "=r"(r1), "=r"(r2), "=r"(r3) : "r"(a));
}
__device__ __forceinline__ void ldm_x4t(unsigned& r0, unsigned& r1, unsigned& r2,
                                        unsigned& r3, unsigned a) {
    asm volatile("ldmatrix.sync.aligned.m8n8.x4.trans.shared.b16 {%0,%1,%2,%3},[%4];"
                 : "=r"(r0), "=r"(r1), "=r"(r2), "=r"(r3) : "r"(a));
}
__device__ __forceinline__ void mma16816(float* c, unsigned a0, unsigned a1,
                                         unsigned a2, unsigned a3,
                                         unsigned b0, unsigned b1) {
    asm volatile(
        "mma.sync.aligned.m16n8k16.row.col.f32.f16.f16.f32 "
        "{%0,%1,%2,%3},{%4,%5,%6,%7},{%8,%9},{%0,%1,%2,%3};"
        : "+f"(c[0]), "+f"(c[1]), "+f"(c[2]), "+f"(c[3])
        : "r"(a0), "r"(a1), "r"(a2), "r"(a3), "r"(b0), "r"(b1));
}

struct LaneGeom { int aRow, aCol, bRow, bCol; };  // aRow includes row0

// one 32-K chunk: 2 ksteps x (1 A-ldmatrix + 4 B-ldmatrix + 8 mma)
__device__ __forceinline__ void mma_chunk(float (*c)[4], unsigned aBase, int lda,
                                          unsigned bBase, int n0, const LaneGeom& lg) {
#pragma unroll
    for (int ks = 0; ks < 2; ++ks) {
        const int k0 = ks * 16;
        unsigned a0, a1, a2, a3;
        ldm_x4(a0, a1, a2, a3,
               aBase + (unsigned)((lg.aRow * lda + k0 + lg.aCol) * 2));
#pragma unroll
        for (int jj = 0; jj < 4; ++jj) {
            unsigned b0, b1, b2, b3;
            ldm_x4t(b0, b1, b2, b3,
                    bBase + (unsigned)(((k0 + lg.bRow) * LDB + n0 + jj * 16 + lg.bCol) * 2));
            mma16816(c[2 * jj],     a0, a1, a2, a3, b0, b1);
            mma16816(c[2 * jj + 1], a0, a1, a2, a3, b2, b3);
        }
    }
}

// B chunk loader: W (fp32 [K][256]) rows kbase..kbase+31 -> bsm fp16 [32][LDB]
__device__ __forceinline__ void load_B_chunk(__half* bsm, const float* W,
                                             int kbase, int tid) {
    const int bk = tid >> 6, bc4 = tid & 63;
#pragma unroll
    for (int p = 0; p < 4; ++p) {
        int kk = bk + p * 8;
        float4 v = *(const float4*)&W[(kbase + kk) * 256 + bc4 * 4];
        __half2* dst = (__half2*)&bsm[kk * LDB + bc4 * 4];
        dst[0] = __floats2half2_rn(v.x, v.y);
        dst[1] = __floats2half2_rn(v.z, v.w);
    }
}

// packed-half2 componentwise atomic max (values >= 0, monotone)
__device__ __forceinline__ void atomic_max_half2(unsigned* p, unsigned vbits) {
    if (vbits == 0u) return;
    unsigned old = *p;
    while (true) {
        __half2 cur = *reinterpret_cast<__half2*>(&old);
        __half2 vv  = *reinterpret_cast<__half2*>(&vbits);
        __half2 mx  = __hmax2(cur, vv);
        unsigned mxb = *reinterpret_cast<unsigned*>(&mx);
        if (mxb == old) return;
        unsigned got = atomicCAS(p, old, mxb);
        if (got == old) return;
        old = got;
    }
}

// ---------------------------------------------------------------------------
// setup kernels (unchanged from passing R6)
// ---------------------------------------------------------------------------
__global__ void init_kernel(int* __restrict__ cnt) {
    int i = blockIdx.x * 256 + threadIdx.x;
    if (i < N_NODES) { g_owner[i] = -1; cnt[i] = 0; }
}
__global__ void owner_scatter_kernel(const int* __restrict__ node_idx) {
    int i = blockIdx.x * 256 + threadIdx.x;
    if (i < BATCH) atomicMax(&g_owner[node_idx[i]], i);
}
__global__ void count_refs_kernel(const int* __restrict__ node_idx,
                                  const int* __restrict__ nbd, int* __restrict__ cnt) {
    int t = blockIdx.x * 256 + threadIdx.x;
    if (t >= NREF) return;
    int i = t >> 4, d = t & 15;
    int n = __ldg(&nbd[__ldg(&node_idx[i]) * DEG + d]);
    atomicAdd(&cnt[n], 1);
}
__global__ void scanA_kernel(const int* __restrict__ cnt) {
    __shared__ int s[1024];
    int b = blockIdx.x, t = threadIdx.x, idx = b * 1024 + t;
    int x = (idx < N_NODES) ? cnt[idx] : 0;
    s[t] = x;
    __syncthreads();
#pragma unroll
    for (int off = 1; off < 1024; off <<= 1) {
        int v = (t >= off) ? s[t - off] : 0;
        __syncthreads();
        s[t] += v;
        __syncthreads();
    }
    if (idx < N_NODES) g_roff[idx] = s[t] - x;
    if (t == 1023) g_bsum[b] = s[1023];
}
__global__ void scanB_kernel() {
    __shared__ int s[64];
    int t = threadIdx.x;
    int x = (t < SCANB) ? g_bsum[t] : 0;
    s[t] = x;
    __syncthreads();
#pragma unroll
    for (int off = 1; off < 64; off <<= 1) {
        int v = (t >= off) ? s[t - off] : 0;
        __syncthreads();
        s[t] += v;
        __syncthreads();
    }
    if (t < SCANB) g_boff[t] = s[t] - x;
}
__global__ void scanC_kernel(int* __restrict__ cursor) {
    int b = blockIdx.x, t = threadIdx.x, idx = b * 1024 + t;
    if (idx < N_NODES) {
        int v = g_roff[idx] + g_boff[b];
        g_roff[idx] = v;
        cursor[idx] = v;
    }
    if (b == 0 && t == 0) g_roff[N_NODES] = NREF;
}
__global__ void fill_refs_kernel(const int* __restrict__ node_idx,
                                 const int* __restrict__ nbd, int* __restrict__ cursor) {
    int t = blockIdx.x * 256 + threadIdx.x;
    if (t >= NREF) return;
    int i = t >> 4, d = t & 15;
    int n = __ldg(&nbd[__ldg(&node_idx[i]) * DEG + d]);
    int p = atomicAdd(&cursor[n], 1);
    g_rlist[p] = i;
}
__global__ void zero_nm2_kernel(float4* __restrict__ nm2) {
    int t = blockIdx.x * 256 + threadIdx.x;
    if (t < (BATCH * 128) / 4) nm2[t] = make_float4(0.f, 0.f, 0.f, 0.f);
}

// ---------------------------------------------------------------------------
// aggb GEMM (mma): aggb[i,:] = relu(feats[i,:] @ W_agg + b) -> fp16 gmem
// ---------------------------------------------------------------------------
__global__ __launch_bounds__(512, 1)
void aggb_gemm_kernel(const float* __restrict__ A, const float* __restrict__ W,
                      const float* __restrict__ bias, __half* __restrict__ C) {
    __shared__ __half asm_[64 * LDA];
    __shared__ __half bsm [32 * LDB];
    __shared__ float  s_b [256];

    const int tx = threadIdx.x, wid = threadIdx.y;
    const int tid = wid * 32 + tx;
    const int rowBase = blockIdx.x * 64;
    const int warpM = wid & 3, warpN = wid >> 2;
    const int row0 = warpM * 16, n0 = warpN * 64;
    const int g = tx >> 2, t4 = tx & 3, q = tx >> 3, rl = tx & 7;
    LaneGeom lg = {row0 + (q & 1) * 8 + rl, (q >> 1) * 8, (q & 1) * 8 + rl, (q >> 1) * 8};
    const int lr = tid >> 3, lk4 = tid & 7;

    if (tid < 256) s_b[tid] = __ldg(&bias[tid]);
    const unsigned asmA = smem_u32(asm_), bsmA = smem_u32(bsm);

    float c[8][4];
#pragma unroll
    for (int j = 0; j < 8; ++j)
#pragma unroll
        for (int k = 0; k < 4; ++k) c[j][k] = 0.f;

#pragma unroll 1
    for (int t = 0; t < 8; ++t) {
        const int kbase = t * 32;
        float4 v = *(const float4*)&A[(rowBase + lr) * 256 + kbase + lk4 * 4];
        __half2* ad = (__half2*)&asm_[lr * LDA + lk4 * 4];
        ad[0] = __floats2half2_rn(v.x, v.y);
        ad[1] = __floats2half2_rn(v.z, v.w);
        load_B_chunk(bsm, W, kbase, tid);
        __syncthreads();
        mma_chunk(c, asmA, LDA, bsmA, n0, lg);
        __syncthreads();
    }

    const int rA = rowBase + row0 + g, rB = rA + 8;
#pragma unroll
    for (int j = 0; j < 8; ++j) {
        int n = n0 + j * 8 + 2 * t4;
        float b0v = s_b[n], b1v = s_b[n + 1];
        *(__half2*)&C[rA * 256 + n] =
            __floats2half2_rn(fmaxf(c[j][0] + b0v, 0.f), fmaxf(c[j][1] + b1v, 0.f));
        *(__half2*)&C[rB * 256 + n] =
            __floats2half2_rn(fmaxf(c[j][2] + b0v, 0.f), fmaxf(c[j][3] + b1v, 0.f));
    }
}

// ---------------------------------------------------------------------------
// sweep (mma): per 64-node tile
//   C: H1 = normalize(relu([H0 | nm1(aggb)] @ W0 + b0)) -> h1h fp16 smem
//   D: agg2 = relu(H1 @ W_agg + b_agg) -> direct register CAS scatter to nm2
// ---------------------------------------------------------------------------
#define SWEEP_SMEM (64*LDH*2 + 32*LDB*2 + 64*LDA*2 + (256+256+64)*4 + 64*DEG*4) // 62208

__global__ __launch_bounds__(512, 1)
void sweep_kernel(const float* __restrict__ feats, const int* __restrict__ nbd,
                  const float* __restrict__ W_agg, const float* __restrict__ b_agg,
                  const float* __restrict__ W0,    const float* __restrict__ b0,
                  const __half* __restrict__ aggb, unsigned* __restrict__ nm2w) {
    extern __shared__ char smp[];
    __half* h1h   = (__half*)smp;                       // [64][264]
    __half* bsm   = h1h + 64 * LDH;                     // [32][264]
    __half* asm_  = bsm + 32 * LDB;                     // [64][40]
    float*  s_bagg = (float*)(asm_ + 64 * LDA);         // 256
    float*  s_bl0  = s_bagg + 256;                      // 256
    float*  ssum   = s_bl0 + 256;                       // 64
    int*    s_nbo  = (int*)(ssum + 64);                 // [64][16]

    const int tx = threadIdx.x, wid = threadIdx.y;
    const int tid = wid * 32 + tx;
    const int rowBase = blockIdx.x * 64;
    const int warpM = wid & 3, warpN = wid >> 2;
    const int row0 = warpM * 16, n0 = warpN * 64;
    const int g = tx >> 2, t4 = tx & 3, q = tx >> 3, rl = tx & 7;
    LaneGeom lg = {row0 + (q & 1) * 8 + rl, (q >> 1) * 8, (q & 1) * 8 + rl, (q >> 1) * 8};
    const int lr = tid >> 3, lk4 = tid & 7;

    if (tid < 256) { s_bagg[tid] = __ldg(&b_agg[tid]); s_bl0[tid] = __ldg(&b0[tid]); }
    if (tid < 64) ssum[tid] = 0.f;
    for (int e = tid; e < 64 * DEG; e += 512) {
        int r = rowBase + (e >> 4);
        int o = -1;
        if (r < N_NODES) o = g_owner[__ldg(&nbd[r * DEG + (e & 15)])];
        s_nbo[e] = o;
    }
    const bool rowOk = (rowBase + lr) < N_NODES;
    const int oSelf = rowOk ? g_owner[rowBase + lr] : -1;

    const unsigned h1hA = smem_u32(h1h), bsmA = smem_u32(bsm), asmA = smem_u32(asm_);

    float c[8][4];
#pragma unroll
    for (int j = 0; j < 8; ++j)
#pragma unroll
        for (int k = 0; k < 4; ++k) c[j][k] = 0.f;

    // ---------------- phase C: K=512 over [H0 | nm1]
#pragma unroll 1
    for (int t = 0; t < 16; ++t) {
        const int kbase = t * 32;
        float4 v = make_float4(0.f, 0.f, 0.f, 0.f);
        if (rowOk) {
            if (t < 8) {
                if (oSelf >= 0)
                    v = *(const float4*)&feats[oSelf * 256 + kbase + lk4 * 4];
            } else {
                const int col = (kbase - 256) + lk4 * 4;
                float4 rb = make_float4(fmaxf(s_bagg[col + 0], 0.f),
                                        fmaxf(s_bagg[col + 1], 0.f),
                                        fmaxf(s_bagg[col + 2], 0.f),
                                        fmaxf(s_bagg[col + 3], 0.f));
                float4 m = make_float4(-1e30f, -1e30f, -1e30f, -1e30f);
                const int* nbo = &s_nbo[lr * DEG];
#pragma unroll
                for (int d = 0; d < DEG; ++d) {
                    int o = nbo[d];
                    float4 w;
                    if (o >= 0) {
                        const __half2* p = (const __half2*)&aggb[o * 256 + col];
                        float2 f01 = __half22float2(__ldg(&p[0]));
                        float2 f23 = __half22float2(__ldg(&p[1]));
                        w = make_float4(f01.x, f01.y, f23.x, f23.y);
                    } else {
                        w = rb;
                    }
                    m.x = fmaxf(m.x, w.x); m.y = fmaxf(m.y, w.y);
                    m.z = fmaxf(m.z, w.z); m.w = fmaxf(m.w, w.w);
                }
                v = m;
            }
        }
        __half2* ad = (__half2*)&asm_[lr * LDA + lk4 * 4];
        ad[0] = __floats2half2_rn(v.x, v.y);
        ad[1] = __floats2half2_rn(v.z, v.w);
        load_B_chunk(bsm, W0, kbase, tid);
        __syncthreads();
        mma_chunk(c, asmA, LDA, bsmA, n0, lg);
        __syncthreads();
    }

    // epilogue C: bias+relu, cross-warp row-norm, write h1h fp16
    const int lrA = row0 + g, lrB = lrA + 8;   // local rows
    {
        float ssA = 0.f, ssB = 0.f;
#pragma unroll
        for (int j = 0; j < 8; ++j) {
            int n = n0 + j * 8 + 2 * t4;
            float b0v = s_bl0[n], b1v = s_bl0[n + 1];
            c[j][0] = fmaxf(c[j][0] + b0v, 0.f);
            c[j][1] = fmaxf(c[j][1] + b1v, 0.f);
            c[j][2] = fmaxf(c[j][2] + b0v, 0.f);
            c[j][3] = fmaxf(c[j][3] + b1v, 0.f);
            ssA = fmaf(c[j][0], c[j][0], fmaf(c[j][1], c[j][1], ssA));
            ssB = fmaf(c[j][2], c[j][2], fmaf(c[j][3], c[j][3], ssB));
        }
        ssA += __shfl_xor_sync(0xffffffffu, ssA, 1);
        ssA += __shfl_xor_sync(0xffffffffu, ssA, 2);
        ssB += __shfl_xor_sync(0xffffffffu, ssB, 1);
        ssB += __shfl_xor_sync(0xffffffffu, ssB, 2);
        if (t4 == 0) { atomicAdd(&ssum[lrA], ssA); atomicAdd(&ssum[lrB], ssB); }
        __syncthreads();
        float invA = 1.f / fmaxf(sqrtf(ssum[lrA]), EPS);
        float invB = 1.f / fmaxf(sqrtf(ssum[lrB]), EPS);
#pragma unroll
        for (int j = 0; j < 8; ++j) {
            int n = n0 + j * 8 + 2 * t4;
            *(__half2*)&h1h[lrA * LDH + n] =
                __floats2half2_rn(c[j][0] * invA, c[j][1] * invA);
            *(__half2*)&h1h[lrB * LDH + n] =
                __floats2half2_rn(c[j][2] * invB, c[j][3] * invB);
        }
    }
    __syncthreads();

    // ---------------- phase D: agg2 = relu(H1 @ W_agg + b), K=256
#pragma unroll
    for (int j = 0; j < 8; ++j)
#pragma unroll
        for (int k = 0; k < 4; ++k) c[j][k] = 0.f;

#pragma unroll 1
    for (int t = 0; t < 8; ++t) {
        load_B_chunk(bsm, W_agg, t * 32, tid);
        __syncthreads();
        mma_chunk(c, h1hA + t * 64, LDH, bsmA, n0, lg);  // +t*32 halves = t*64 bytes
        __syncthreads();
    }

    // epilogue D: bias+relu -> half2 bits, direct CAS scatter via CSR
    unsigned wA[8], wB[8];
#pragma unroll
    for (int j = 0; j < 8; ++j) {
        int n = n0 + j * 8 + 2 * t4;
        float b0v = s_bagg[n], b1v = s_bagg[n + 1];
        __half2 hA = __floats2half2_rn(fmaxf(c[j][0] + b0v, 0.f),
                                       fmaxf(c[j][1] + b1v, 0.f));
        __half2 hB = __floats2half2_rn(fmaxf(c[j][2] + b0v, 0.f),
                                       fmaxf(c[j][3] + b1v, 0.f));
        wA[j] = *reinterpret_cast<unsigned*>(&hA);
        wB[j] = *reinterpret_cast<unsigned*>(&hB);
    }
    {
        int r = rowBase + lrA;
        if (r < N_NODES) {
            int s = g_roff[r], e = g_roff[r + 1];
            for (int m = s; m < e; ++m) {
                unsigned* dst = nm2w + g_rlist[m] * 128 + (n0 >> 1) + t4;
#pragma unroll
                for (int j = 0; j < 8; ++j) atomic_max_half2(dst + j * 4, wA[j]);
            }
        }
        r = rowBase + lrB;
        if (r < N_NODES) {
            int s = g_roff[r], e = g_roff[r + 1];
            for (int m = s; m < e; ++m) {
                unsigned* dst = nm2w + g_rlist[m] * 128 + (n0 >> 1) + t4;
#pragma unroll
                for (int j = 0; j < 8; ++j) atomic_max_half2(dst + j * 4, wB[j]);
            }
        }
    }
}

// ---------------------------------------------------------------------------
// final (mma, 128 co-resident blocks, grid barrier):
//   pre : C' recompute H1 for 64 batch rows -> h1h; copy nm2 rows -> nm2h
//   barrier
//   post: out = normalize(relu([H1 | nm2] @ W1 + b1)) -> d_out fp32
// ---------------------------------------------------------------------------
#define FINAL_SMEM (64*LDH*2*2 + 32*LDB*2 + 64*LDA*2 + (256*3+64)*4 + 64*DEG*4) // 97024

__global__ __launch_bounds__(512, 1)
void final_kernel(const int* __restrict__ node_idx, const float* __restrict__ feats,
                  const int* __restrict__ nbd,
                  const float* __restrict__ W0, const float* __restrict__ b0,
                  const float* __restrict__ W1, const float* __restrict__ b1,
                  const float* __restrict__ b_agg,
                  const __half* __restrict__ aggb, const unsigned* __restrict__ nm2w,
                  float* __restrict__ out) {
    extern __shared__ char smp[];
    __half* h1h   = (__half*)smp;                       // [64][264]
    __half* nm2h  = h1h + 64 * LDH;                     // [64][264]
    __half* bsm   = nm2h + 64 * LDH;                    // [32][264]
    __half* asm_  = bsm + 32 * LDB;                     // [64][40]
    float*  s_bagg = (float*)(asm_ + 64 * LDA);
    float*  s_bl0  = s_bagg + 256;
    float*  s_bl1  = s_bl0 + 256;
    float*  ssum   = s_bl1 + 256;                       // 64
    int*    s_nbo  = (int*)(ssum + 64);

    const int tx = threadIdx.x, wid = threadIdx.y;
    const int tid = wid * 32 + tx;
    const int rowBase = blockIdx.x * 64;
    const int warpM = wid & 3, warpN = wid >> 2;
    const int row0 = warpM * 16, n0 = warpN * 64;
    const int g = tx >> 2, t4 = tx & 3, q = tx >> 3, rl = tx & 7;
    LaneGeom lg = {row0 + (q & 1) * 8 + rl, (q >> 1) * 8, (q & 1) * 8 + rl, (q >> 1) * 8};
    const int lr = tid >> 3, lk4 = tid & 7;

    if (tid < 256) {
        s_bagg[tid] = __ldg(&b_agg[tid]);
        s_bl0[tid]  = __ldg(&b0[tid]);
        s_bl1[tid]  = __ldg(&b1[tid]);
    }
    if (tid < 64) ssum[tid] = 0.f;
    for (int e = tid; e < 64 * DEG; e += 512) {
        int x = __ldg(&node_idx[rowBase + (e >> 4)]);
        s_nbo[e] = g_owner[__ldg(&nbd[x * DEG + (e & 15)])];
    }
    const int oSelf = g_owner[__ldg(&node_idx[rowBase + lr])];

    const unsigned h1hA = smem_u32(h1h), nm2hA = smem_u32(nm2h);
    const unsigned bsmA = smem_u32(bsm), asmA = smem_u32(asm_);

    float c[8][4];
#pragma unroll
    for (int j = 0; j < 8; ++j)
#pragma unroll
        for (int k = 0; k < 4; ++k) c[j][k] = 0.f;

    // ---------------- phase C': H1 for batch rows (reads aggb — pre-barrier)
#pragma unroll 1
    for (int t = 0; t < 16; ++t) {
        const int kbase = t * 32;
        float4 v = make_float4(0.f, 0.f, 0.f, 0.f);
        if (t < 8) {
            if (oSelf >= 0)
                v = *(const float4*)&feats[oSelf * 256 + kbase + lk4 * 4];
        } else {
            const int col = (kbase - 256) + lk4 * 4;
            float4 rb = make_float4(fmaxf(s_bagg[col + 0], 0.f),
                                    fmaxf(s_bagg[col + 1], 0.f),
                                    fmaxf(s_bagg[col + 2], 0.f),
                                    fmaxf(s_bagg[col + 3], 0.f));
            float4 m = make_float4(-1e30f, -1e30f, -1e30f, -1e30f);
            const int* nbo = &s_nbo[lr * DEG];
#pragma unroll
            for (int d = 0; d < DEG; ++d) {
                int o = nbo[d];
                float4 w;
                if (o >= 0) {
                    const __half2* p = (const __half2*)&aggb[o * 256 + col];
                    float2 f01 = __half22float2(__ldg(&p[0]));
                    float2 f23 = __half22float2(__ldg(&p[1]));
                    w = make_float4(f01.x, f01.y, f23.x, f23.y);
                } else {
                    w = rb;
                }
                m.x = fmaxf(m.x, w.x); m.y = fmaxf(m.y, w.y);
                m.z = fmaxf(m.z, w.z); m.w = fmaxf(m.w, w.w);
            }
            v = m;
        }
        __half2* ad = (__half2*)&asm_[lr * LDA + lk4 * 4];
        ad[0] = __floats2half2_rn(v.x, v.y);
        ad[1] = __floats2half2_rn(v.z, v.w);
        load_B_chunk(bsm, W0, kbase, tid);
        __syncthreads();
        mma_chunk(c, asmA, LDA, bsmA, n0, lg);
        __syncthreads();
    }

    const int lrA = row0 + g, lrB = lrA + 8;
    {   // epilogue C' -> h1h
        float ssA = 0.f, ssB = 0.f;
#pragma unroll
        for (int j = 0; j < 8; ++j) {
            int n = n0 + j * 8 + 2 * t4;
            float b0v = s_bl0[n], b1v = s_bl0[n + 1];
            c[j][0] = fmaxf(c[j][0] + b0v, 0.f);
            c[j][1] = fmaxf(c[j][1] + b1v, 0.f);
            c[j][2] = fmaxf(c[j][2] + b0v, 0.f);
            c[j][3] = fmaxf(c[j][3] + b1v, 0.f);
            ssA = fmaf(c[j][0], c[j][0], fmaf(c[j][1], c[j][1], ssA));
            ssB = fmaf(c[j][2], c[j][2], fmaf(c[j][3], c[j][3], ssB));
        }
        ssA += __shfl_xor_sync(0xffffffffu, ssA, 1);
        ssA += __shfl_xor_sync(0xffffffffu, ssA, 2);
        ssB += __shfl_xor_sync(0xffffffffu, ssB, 1);
        ssB += __shfl_xor_sync(0xffffffffu, ssB, 2);
        if (t4 == 0) { atomicAdd(&ssum[lrA], ssA); atomicAdd(&ssum[lrB], ssB); }
        __syncthreads();
        float invA = 1.f / fmaxf(sqrtf(ssum[lrA]), EPS);
        float invB = 1.f / fmaxf(sqrtf(ssum[lrB]), EPS);
#pragma unroll
        for (int j = 0; j < 8; ++j) {
            int n = n0 + j * 8 + 2 * t4;
            *(__half2*)&h1h[lrA * LDH + n] =
                __floats2half2_rn(c[j][0] * invA, c[j][1] * invA);
            *(__half2*)&h1h[lrB * LDH + n] =
                __floats2half2_rn(c[j][2] * invB, c[j][3] * invB);
        }
    }
    __syncthreads();
    if (tid < 64) ssum[tid] = 0.f;            // re-arm for D'

    // copy own nm2 rows -> smem (pre-barrier read of d_out region2)
    {
        unsigned* nw = (unsigned*)nm2h;
        for (int w = tid; w < 64 * 128; w += 512) {
            int r = w >> 7, wi = w & 127;
            nw[r * (LDH / 2) + wi] = __ldg(&nm2w[(rowBase + r) * 128 + wi]);
        }
    }
    __syncthreads();

    // ---- manual grid barrier (128 blocks co-resident; self-resetting) ----
    if (tid == 0) {
        unsigned phase = atomicAdd(&g_barPhase, 0u);
        unsigned t = atomicAdd(&g_barCount, 1u);
        if (t == gridDim.x - 1) {
            g_barCount = 0u;
            __threadfence();
            atomicAdd(&g_barPhase, 1u);
        } else {
            while (atomicAdd(&g_barPhase, 0u) == phase) { }
        }
    }
    __syncthreads();

    // ---------------- phase D': out = normalize(relu([H1|nm2] @ W1 + b1))
#pragma unroll
    for (int j = 0; j < 8; ++j)
#pragma unroll
        for (int k = 0; k < 4; ++k) c[j][k] = 0.f;

#pragma unroll 1
    for (int t = 0; t < 16; ++t) {
        load_B_chunk(bsm, W1, t * 32, tid);
        __syncthreads();
        unsigned aB = (t < 8) ? (h1hA + t * 64) : (nm2hA + (t - 8) * 64);
        mma_chunk(c, aB, LDH, bsmA, n0, lg);
        __syncthreads();
    }

    {   // epilogue D' -> out (fp32)
        float ssA = 0.f, ssB = 0.f;
#pragma unroll
        for (int j = 0; j < 8; ++j) {
            int n = n0 + j * 8 + 2 * t4;
            float b0v = s_bl1[n], b1v = s_bl1[n + 1];
            c[j][0] = fmaxf(c[j][0] + b0v, 0.f);
            c[j][1] = fmaxf(c[j][1] + b1v, 0.f);
            c[j][2] = fmaxf(c[j][2] + b0v, 0.f);
            c[j][3] = fmaxf(c[j][3] + b1v, 0.f);
            ssA = fmaf(c[j][0], c[j][0], fmaf(c[j][1], c[j][1], ssA));
            ssB = fmaf(c[j][2], c[j][2], fmaf(c[j][3], c[j][3], ssB));
        }
        ssA += __shfl_xor_sync(0xffffffffu, ssA, 1);
        ssA += __shfl_xor_sync(0xffffffffu, ssA, 2);
        ssB += __shfl_xor_sync(0xffffffffu, ssB, 1);
        ssB += __shfl_xor_sync(0xffffffffu, ssB, 2);
        if (t4 == 0) { atomicAdd(&ssum[lrA], ssA); atomicAdd(&ssum[lrB], ssB); }
        __syncthreads();
        float invA = 1.f / fmaxf(sqrtf(ssum[lrA]), EPS);
        float invB = 1.f / fmaxf(sqrtf(ssum[lrB]), EPS);
#pragma unroll
        for (int j = 0; j < 8; ++j) {
            int n = n0 + j * 8 + 2 * t4;
            *(float2*)&out[(rowBase + lrA) * 256 + n] =
                make_float2(c[j][0] * invA, c[j][1] * invA);
            *(float2*)&out[(rowBase + lrB) * 256 + n] =
                make_float2(c[j][2] * invB, c[j][3] * invB);
        }
    }
}

// ---------------------------------------------------------------------------
// launch: node_idx, feats, nbd, W_agg, b_agg, W_lin, b_lin  -> out [B,256]
// ---------------------------------------------------------------------------
extern "C" void kernel_launch(void* const* d_in, const int* in_sizes, int n_in,
                              void* d_out, int out_size) {
    const int*   node_idx = (const int*)d_in[0];
    const float* feats    = (const float*)d_in[1];
    const int*   nbd      = (const int*)d_in[2];
    const float* W_agg    = (const float*)d_in[3];
    const float* b_agg    = (const float*)d_in[4];
    const float* W_lin    = (const float*)d_in[5];  // [2, 512, 256]
    const float* b_lin    = (const float*)d_in[6];  // [2, 256]

    __half*   aggb = (__half*)d_out;
    unsigned* nm2w = (unsigned*)((char*)d_out + AGGB_BYTES);
    float*    out  = (float*)d_out;
    int*      cnt  = (int*)d_out;   // setup-phase scratch (dead before aggb GEMM)

    cudaFuncSetAttribute(sweep_kernel,
                         cudaFuncAttributeMaxDynamicSharedMemorySize, SWEEP_SMEM);
    cudaFuncSetAttribute(final_kernel,
                         cudaFuncAttributeMaxDynamicSharedMemorySize, FINAL_SMEM);

    dim3 gblk(32, 16);
    const int gridN = (N_NODES + 63) / 64;   // 782
    const int gridB = BATCH / 64;            // 128

    init_kernel<<<(N_NODES + 255) / 256, 256>>>(cnt);
    owner_scatter_kernel<<<(BATCH + 255) / 256, 256>>>(node_idx);
    count_refs_kernel<<<NREF / 256, 256>>>(node_idx, nbd, cnt);
    scanA_kernel<<<SCANB, 1024>>>(cnt);
    scanB_kernel<<<1, 64>>>();
    scanC_kernel<<<SCANB, 1024>>>(cnt);
    fill_refs_kernel<<<NREF / 256, 256>>>(node_idx, nbd, cnt);

    aggb_gemm_kernel<<<gridB, gblk>>>(feats, W_agg, b_agg, aggb);
    zero_nm2_kernel<<<(BATCH * 128 / 4 + 255) / 256, 256>>>((float4*)nm2w);
    sweep_kernel<<<gridN, gblk, SWEEP_SMEM>>>(
        feats, nbd, W_agg, b_agg, W_lin, b_lin, aggb, nm2w);
    final_kernel<<<gridB, gblk, FINAL_SMEM>>>(
        node_idx, feats, nbd, W_lin, b_lin,
        W_lin + 512 * 256, b_lin + 256, b_agg, aggb, nm2w, out);
}

// round 8
// speedup vs baseline: 1.8671x; 1.8671x over previous
#include <cuda_runtime.h>
#include <cuda_fp16.h>
#include <math.h>

#define N_NODES 50000
#define DEG     16
#define WIDTH   256
#define BATCH   8192
#define EPS     1e-12f

#define LDA 40     // A staging leading dim (halves): 80B rows
#define LDB 264    // B staging leading dim (halves): 528B rows
#define LDH 264    // H1/nm2 smem leading dim (halves)

// ---- device globals: ~0.2MB (big scratch lives in d_out) ----
__device__ int      g_owner[N_NODES];     // last batch writer (-1 none)
__device__ unsigned g_barCount;           // manual grid barrier (self-resetting)
__device__ unsigned g_barPhase;

// ---------------------------------------------------------------------------
// mma helpers (validated in R7)
// ---------------------------------------------------------------------------
__device__ __forceinline__ unsigned smem_u32(const void* p) {
    return (unsigned)__cvta_generic_to_shared(p);
}
__device__ __forceinline__ void ldm_x4(unsigned& r0, unsigned& r1, unsigned& r2,
                                       unsigned& r3, unsigned a) {
    asm volatile("ldmatrix.sync.aligned.m8n8.x4.shared.b16 {%0,%1,%2,%3},[%4];"
                 : "=r"(r0), "=r"(r1), "=r"(r2), "=r"(r3) : "r"(a));
}
__device__ __forceinline__ void ldm_x4t(unsigned& r0, unsigned& r1, unsigned& r2,
                                        unsigned& r3, unsigned a) {
    asm volatile("ldmatrix.sync.aligned.m8n8.x4.trans.shared.b16 {%0,%1,%2,%3},[%4];"
                 : "=r"(r0), "=r"(r1), "=r"(r2), "=r"(r3) : "r"(a));
}
__device__ __forceinline__ void mma16816(float* c, unsigned a0, unsigned a1,
                                         unsigned a2, unsigned a3,
                                         unsigned b0, unsigned b1) {
    asm volatile(
        "mma.sync.aligned.m16n8k16.row.col.f32.f16.f16.f32 "
        "{%0,%1,%2,%3},{%4,%5,%6,%7},{%8,%9},{%0,%1,%2,%3};"
        : "+f"(c[0]), "+f"(c[1]), "+f"(c[2]), "+f"(c[3])
        : "r"(a0), "r"(a1), "r"(a2), "r"(a3), "r"(b0), "r"(b1));
}

struct LaneGeom { int aRow, aCol, bRow, bCol; };

__device__ __forceinline__ void mma_chunk(float (*c)[4], unsigned aBase, int lda,
                                          unsigned bBase, int n0, const LaneGeom& lg) {
#pragma unroll
    for (int ks = 0; ks < 2; ++ks) {
        const int k0 = ks * 16;
        unsigned a0, a1, a2, a3;
        ldm_x4(a0, a1, a2, a3,
               aBase + (unsigned)((lg.aRow * lda + k0 + lg.aCol) * 2));
#pragma unroll
        for (int jj = 0; jj < 4; ++jj) {
            unsigned b0, b1, b2, b3;
            ldm_x4t(b0, b1, b2, b3,
                    bBase + (unsigned)(((k0 + lg.bRow) * LDB + n0 + jj * 16 + lg.bCol) * 2));
            mma16816(c[2 * jj],     a0, a1, a2, a3, b0, b1);
            mma16816(c[2 * jj + 1], a0, a1, a2, a3, b2, b3);
        }
    }
}

__device__ __forceinline__ void load_B_chunk(__half* bsm, const float* W,
                                             int kbase, int tid) {
    const int bk = tid >> 6, bc4 = tid & 63;
#pragma unroll
    for (int p = 0; p < 4; ++p) {
        int kk = bk + p * 8;
        float4 v = *(const float4*)&W[(kbase + kk) * 256 + bc4 * 4];
        __half2* dst = (__half2*)&bsm[kk * LDB + bc4 * 4];
        dst[0] = __floats2half2_rn(v.x, v.y);
        dst[1] = __floats2half2_rn(v.z, v.w);
    }
}

// ---------------------------------------------------------------------------
// setup kernels
// ---------------------------------------------------------------------------
__global__ void init_owner_kernel() {
    int i = blockIdx.x * 256 + threadIdx.x;
    if (i < N_NODES) g_owner[i] = -1;
}
__global__ void owner_scatter_kernel(const int* __restrict__ node_idx) {
    int i = blockIdx.x * 256 + threadIdx.x;
    if (i < BATCH) atomicMax(&g_owner[node_idx[i]], i);   // last-wins on dups
}

// ---------------------------------------------------------------------------
// aggb GEMM: aggb[i,:] = relu(feats[i,:] @ W_agg + b) -> fp16 (d_out region1)
// ---------------------------------------------------------------------------
__global__ __launch_bounds__(512, 1)
void aggb_gemm_kernel(const float* __restrict__ A, const float* __restrict__ W,
                      const float* __restrict__ bias, __half* __restrict__ C) {
    __shared__ __half asm_[64 * LDA];
    __shared__ __half bsm [32 * LDB];
    __shared__ float  s_b [256];

    const int tx = threadIdx.x, wid = threadIdx.y;
    const int tid = wid * 32 + tx;
    const int rowBase = blockIdx.x * 64;
    const int warpM = wid & 3, warpN = wid >> 2;
    const int row0 = warpM * 16, n0 = warpN * 64;
    const int g = tx >> 2, t4 = tx & 3, q = tx >> 3, rl = tx & 7;
    LaneGeom lg = {row0 + (q & 1) * 8 + rl, (q >> 1) * 8, (q & 1) * 8 + rl, (q >> 1) * 8};
    const int lr = tid >> 3, lk4 = tid & 7;

    if (tid < 256) s_b[tid] = __ldg(&bias[tid]);
    const unsigned asmA = smem_u32(asm_), bsmA = smem_u32(bsm);

    float c[8][4];
#pragma unroll
    for (int j = 0; j < 8; ++j)
#pragma unroll
        for (int k = 0; k < 4; ++k) c[j][k] = 0.f;

#pragma unroll 1
    for (int t = 0; t < 8; ++t) {
        const int kbase = t * 32;
        float4 v = *(const float4*)&A[(rowBase + lr) * 256 + kbase + lk4 * 4];
        __half2* ad = (__half2*)&asm_[lr * LDA + lk4 * 4];
        ad[0] = __floats2half2_rn(v.x, v.y);
        ad[1] = __floats2half2_rn(v.z, v.w);
        load_B_chunk(bsm, W, kbase, tid);
        __syncthreads();
        mma_chunk(c, asmA, LDA, bsmA, n0, lg);
        __syncthreads();
    }

    const int rA = rowBase + row0 + g, rB = rA + 8;
#pragma unroll
    for (int j = 0; j < 8; ++j) {
        int n = n0 + j * 8 + 2 * t4;
        float b0v = s_b[n], b1v = s_b[n + 1];
        *(__half2*)&C[rA * 256 + n] =
            __floats2half2_rn(fmaxf(c[j][0] + b0v, 0.f), fmaxf(c[j][1] + b1v, 0.f));
        *(__half2*)&C[rB * 256 + n] =
            __floats2half2_rn(fmaxf(c[j][2] + b0v, 0.f), fmaxf(c[j][3] + b1v, 0.f));
    }
}

// ---------------------------------------------------------------------------
// H1 tile builder (shared by self tile + 16 neighbor tiles):
//   dstH1[r,:] = normalize(relu([H0(r) | nm1(r)] @ W0 + b0))  (64 rows, fp16)
// H0(r) = feats[oArr[r]] (or 0); nm1(r) = max_d agg1(nboArr[r*16+d]) with
// agg1 = aggb[o] if owned else relu(b_agg). Assumes ssum[]==0 on entry;
// leaves ssum[]==0 and dstH1 visible on exit.
// ---------------------------------------------------------------------------
__device__ __forceinline__ void compute_h1_tile(
    const float* __restrict__ feats, const __half* __restrict__ aggb,
    const int* __restrict__ oArr, const int* __restrict__ nboArr,
    const float* __restrict__ s_bagg, const float* __restrict__ s_bl0,
    float* __restrict__ ssum, __half* __restrict__ dstH1,
    __half* __restrict__ asm_, __half* __restrict__ bsm,
    const float* __restrict__ W0,
    int tid, int n0, const LaneGeom& lg, int lrA, int lrB2, int t4) {

    const int lr = tid >> 3, lk4 = tid & 7;
    const unsigned asmA = smem_u32(asm_), bsmA = smem_u32(bsm);

    float c[8][4];
#pragma unroll
    for (int j = 0; j < 8; ++j)
#pragma unroll
        for (int k = 0; k < 4; ++k) c[j][k] = 0.f;

#pragma unroll 1
    for (int t = 0; t < 16; ++t) {
        const int kbase = t * 32;
        float4 v = make_float4(0.f, 0.f, 0.f, 0.f);
        if (t < 8) {                       // H0 half
            int o = oArr[lr];
            if (o >= 0)
                v = *(const float4*)&feats[o * 256 + kbase + lk4 * 4];
        } else {                           // nm1 half: max over 16 neighbors
            const int col = (kbase - 256) + lk4 * 4;
            float4 rb = make_float4(fmaxf(s_bagg[col + 0], 0.f),
                                    fmaxf(s_bagg[col + 1], 0.f),
                                    fmaxf(s_bagg[col + 2], 0.f),
                                    fmaxf(s_bagg[col + 3], 0.f));
            float4 m = make_float4(-1e30f, -1e30f, -1e30f, -1e30f);
            const int* nbo = &nboArr[lr * DEG];
#pragma unroll
            for (int d = 0; d < DEG; ++d) {
                int o = nbo[d];
                float4 w;
                if (o >= 0) {
                    const __half2* p = (const __half2*)&aggb[o * 256 + col];
                    float2 f01 = __half22float2(__ldg(&p[0]));
                    float2 f23 = __half22float2(__ldg(&p[1]));
                    w = make_float4(f01.x, f01.y, f23.x, f23.y);
                } else {
                    w = rb;
                }
                m.x = fmaxf(m.x, w.x); m.y = fmaxf(m.y, w.y);
                m.z = fmaxf(m.z, w.z); m.w = fmaxf(m.w, w.w);
            }
            v = m;
        }
        __half2* ad = (__half2*)&asm_[lr * LDA + lk4 * 4];
        ad[0] = __floats2half2_rn(v.x, v.y);
        ad[1] = __floats2half2_rn(v.z, v.w);
        load_B_chunk(bsm, W0, kbase, tid);
        __syncthreads();
        mma_chunk(c, asmA, LDA, bsmA, n0, lg);
        __syncthreads();
    }

    // epilogue: bias+relu, row-norm (cross-warpN via smem atomics), write fp16
    float ssA = 0.f, ssB = 0.f;
#pragma unroll
    for (int j = 0; j < 8; ++j) {
        int n = n0 + j * 8 + 2 * t4;
        float b0v = s_bl0[n], b1v = s_bl0[n + 1];
        c[j][0] = fmaxf(c[j][0] + b0v, 0.f);
        c[j][1] = fmaxf(c[j][1] + b1v, 0.f);
        c[j][2] = fmaxf(c[j][2] + b0v, 0.f);
        c[j][3] = fmaxf(c[j][3] + b1v, 0.f);
        ssA = fmaf(c[j][0], c[j][0], fmaf(c[j][1], c[j][1], ssA));
        ssB = fmaf(c[j][2], c[j][2], fmaf(c[j][3], c[j][3], ssB));
    }
    ssA += __shfl_xor_sync(0xffffffffu, ssA, 1);
    ssA += __shfl_xor_sync(0xffffffffu, ssA, 2);
    ssB += __shfl_xor_sync(0xffffffffu, ssB, 1);
    ssB += __shfl_xor_sync(0xffffffffu, ssB, 2);
    if (t4 == 0) { atomicAdd(&ssum[lrA], ssA); atomicAdd(&ssum[lrB2], ssB); }
    __syncthreads();
    float invA = 1.f / fmaxf(sqrtf(ssum[lrA]), EPS);
    float invB = 1.f / fmaxf(sqrtf(ssum[lrB2]), EPS);
    __syncthreads();
    if (tid < 64) ssum[tid] = 0.f;     // re-arm for next use
#pragma unroll
    for (int j = 0; j < 8; ++j) {
        int n = n0 + j * 8 + 2 * t4;
        *(__half2*)&dstH1[lrA * LDH + n]  =
            __floats2half2_rn(c[j][0] * invA, c[j][1] * invA);
        *(__half2*)&dstH1[lrB2 * LDH + n] =
            __floats2half2_rn(c[j][2] * invB, c[j][3] * invB);
    }
    __syncthreads();
}

// ---------------------------------------------------------------------------
// final2: one block per 64 batch rows; recomputes everything locally.
//   selfH1 tile; 16 neighbor tiles -> H1 -> agg2 -> warp group-max -> nm2;
//   out = normalize(relu([selfH1 | nm2] @ W1 + b1)); grid barrier; write.
// ---------------------------------------------------------------------------
#define F2_SMEM (3*64*LDH*2 + 32*LDB*2 + 64*LDA*2 + (256*3+64)*4 + (64*4 + 2*64*DEG)*4)

__global__ __launch_bounds__(512, 1)
void final2_kernel(const int* __restrict__ node_idx, const float* __restrict__ feats,
                   const int* __restrict__ nbd,
                   const float* __restrict__ W_agg, const float* __restrict__ b_agg,
                   const float* __restrict__ W0, const float* __restrict__ b0,
                   const float* __restrict__ W1, const float* __restrict__ b1,
                   const __half* __restrict__ aggb, float* __restrict__ out) {
    extern __shared__ char smp[];
    __half* selfH1 = (__half*)smp;                 // [64][264]
    __half* h1t    = selfH1 + 64 * LDH;            // [64][264]
    __half* nm2    = h1t    + 64 * LDH;            // [64][264]
    __half* bsm    = nm2    + 64 * LDH;            // [32][264]
    __half* asm_   = bsm    + 32 * LDB;            // [64][40]
    float*  s_bagg = (float*)(asm_ + 64 * LDA);    // 256
    float*  s_bl0  = s_bagg + 256;                 // 256
    float*  s_bl1  = s_bl0 + 256;                  // 256
    float*  ssum   = s_bl1 + 256;                  // 64
    int*    xs     = (int*)(ssum + 64);            // 64
    int*    oS     = xs + 64;                      // 64
    int*    oT     = oS + 64;                      // 64
    int*    s_nid  = oT + 64;                      // 64
    int*    nboS   = s_nid + 64;                   // 1024
    int*    nboT   = nboS + 1024;                  // 1024

    const int tx = threadIdx.x, wid = threadIdx.y;
    const int tid = wid * 32 + tx;
    const int rB = blockIdx.x * 64;
    const int warpM = wid & 3, warpN = wid >> 2;
    const int row0 = warpM * 16, n0 = warpN * 64;
    const int g = tx >> 2, t4 = tx & 3, q = tx >> 3, rl = tx & 7;
    LaneGeom lg = {row0 + (q & 1) * 8 + rl, (q >> 1) * 8, (q & 1) * 8 + rl, (q >> 1) * 8};
    const int lrA = row0 + g, lrB2 = lrA + 8;

    if (tid < 256) {
        s_bagg[tid] = __ldg(&b_agg[tid]);
        s_bl0[tid]  = __ldg(&b0[tid]);
        s_bl1[tid]  = __ldg(&b1[tid]);
    }
    if (tid < 64) {
        ssum[tid] = 0.f;
        int x = __ldg(&node_idx[rB + tid]);
        xs[tid] = x;
        oS[tid] = g_owner[x];
    }
    __syncthreads();
    for (int e = tid; e < 64 * DEG; e += 512)
        nboS[e] = g_owner[__ldg(&nbd[xs[e >> 4] * DEG + (e & 15)])];
    __syncthreads();

    const unsigned selfA = smem_u32(selfH1), h1tA = smem_u32(h1t);
    const unsigned nm2A  = smem_u32(nm2),   bsmA = smem_u32(bsm);

    // ---- self H1 tile ----
    compute_h1_tile(feats, aggb, oS, nboS, s_bagg, s_bl0, ssum, selfH1,
                    asm_, bsm, W0, tid, n0, lg, lrA, lrB2, t4);

    // ---- 16 neighbor tiles: H1 -> agg2 -> group-max into nm2 ----
#pragma unroll 1
    for (int nt = 0; nt < 16; ++nt) {
        if (tid < 64) {
            int il = nt * 4 + (tid >> 4);
            int n = __ldg(&nbd[xs[il] * DEG + (tid & 15)]);
            s_nid[tid] = n;
            oT[tid] = g_owner[n];
        }
        __syncthreads();
        for (int e = tid; e < 64 * DEG; e += 512)
            nboT[e] = g_owner[__ldg(&nbd[s_nid[e >> 4] * DEG + (e & 15)])];
        __syncthreads();

        compute_h1_tile(feats, aggb, oT, nboT, s_bagg, s_bl0, ssum, h1t,
                        asm_, bsm, W0, tid, n0, lg, lrA, lrB2, t4);

        // agg2 = relu(h1t @ W_agg + b_agg)
        float c[8][4];
#pragma unroll
        for (int j = 0; j < 8; ++j)
#pragma unroll
            for (int k = 0; k < 4; ++k) c[j][k] = 0.f;
#pragma unroll 1
        for (int t = 0; t < 8; ++t) {
            load_B_chunk(bsm, W_agg, t * 32, tid);
            __syncthreads();
            mma_chunk(c, h1tA + t * 64, LDH, bsmA, n0, lg);
            __syncthreads();
        }
        // bias+relu, then max over the warpM group's 16 rows (rows of one
        // batch entry i = rB + nt*4 + warpM): register + shfl reduction.
#pragma unroll
        for (int j = 0; j < 8; ++j) {
            int n = n0 + j * 8 + 2 * t4;
            float b0v = s_bagg[n], b1v = s_bagg[n + 1];
            float a0 = fmaxf(fmaxf(c[j][0] + b0v, 0.f), fmaxf(c[j][2] + b0v, 0.f));
            float a1 = fmaxf(fmaxf(c[j][1] + b1v, 0.f), fmaxf(c[j][3] + b1v, 0.f));
#pragma unroll
            for (int mask = 4; mask <= 16; mask <<= 1) {
                a0 = fmaxf(a0, __shfl_xor_sync(0xffffffffu, a0, mask));
                a1 = fmaxf(a1, __shfl_xor_sync(0xffffffffu, a1, mask));
            }
            *(__half2*)&nm2[(nt * 4 + warpM) * LDH + n] = __floats2half2_rn(a0, a1);
        }
        __syncthreads();
    }

    // ---- final GEMM: [selfH1 | nm2] @ W1, K=512 ----
    float c[8][4];
#pragma unroll
    for (int j = 0; j < 8; ++j)
#pragma unroll
        for (int k = 0; k < 4; ++k) c[j][k] = 0.f;
#pragma unroll 1
    for (int t = 0; t < 16; ++t) {
        load_B_chunk(bsm, W1, t * 32, tid);
        __syncthreads();
        unsigned aB = (t < 8) ? (selfA + t * 64) : (nm2A + (t - 8) * 64);
        mma_chunk(c, aB, LDH, bsmA, n0, lg);
        __syncthreads();
    }

    // epilogue: bias+relu+normalize, values kept in registers across barrier
    float invA, invB;
    {
        float ssA = 0.f, ssB = 0.f;
#pragma unroll
        for (int j = 0; j < 8; ++j) {
            int n = n0 + j * 8 + 2 * t4;
            float b0v = s_bl1[n], b1v = s_bl1[n + 1];
            c[j][0] = fmaxf(c[j][0] + b0v, 0.f);
            c[j][1] = fmaxf(c[j][1] + b1v, 0.f);
            c[j][2] = fmaxf(c[j][2] + b0v, 0.f);
            c[j][3] = fmaxf(c[j][3] + b1v, 0.f);
            ssA = fmaf(c[j][0], c[j][0], fmaf(c[j][1], c[j][1], ssA));
            ssB = fmaf(c[j][2], c[j][2], fmaf(c[j][3], c[j][3], ssB));
        }
        ssA += __shfl_xor_sync(0xffffffffu, ssA, 1);
        ssA += __shfl_xor_sync(0xffffffffu, ssA, 2);
        ssB += __shfl_xor_sync(0xffffffffu, ssB, 1);
        ssB += __shfl_xor_sync(0xffffffffu, ssB, 2);
        if (t4 == 0) { atomicAdd(&ssum[lrA], ssA); atomicAdd(&ssum[lrB2], ssB); }
        __syncthreads();
        invA = 1.f / fmaxf(sqrtf(ssum[lrA]), EPS);
        invB = 1.f / fmaxf(sqrtf(ssum[lrB2]), EPS);
    }

    // ---- grid barrier: all aggb reads done before out overwrites d_out ----
    __syncthreads();
    if (tid == 0) {
        unsigned phase = atomicAdd(&g_barPhase, 0u);
        unsigned t = atomicAdd(&g_barCount, 1u);
        if (t == gridDim.x - 1) {
            g_barCount = 0u;
            __threadfence();
            atomicAdd(&g_barPhase, 1u);
        } else {
            while (atomicAdd(&g_barPhase, 0u) == phase) { }
        }
    }
    __syncthreads();

    // ---- write out ----
#pragma unroll
    for (int j = 0; j < 8; ++j) {
        int n = n0 + j * 8 + 2 * t4;
        *(float2*)&out[(rB + lrA) * 256 + n] =
            make_float2(c[j][0] * invA, c[j][1] * invA);
        *(float2*)&out[(rB + lrB2) * 256 + n] =
            make_float2(c[j][2] * invB, c[j][3] * invB);
    }
}

// ---------------------------------------------------------------------------
// launch: node_idx, feats, nbd, W_agg, b_agg, W_lin, b_lin  -> out [B,256]
// ---------------------------------------------------------------------------
extern "C" void kernel_launch(void* const* d_in, const int* in_sizes, int n_in,
                              void* d_out, int out_size) {
    const int*   node_idx = (const int*)d_in[0];
    const float* feats    = (const float*)d_in[1];
    const int*   nbd      = (const int*)d_in[2];
    const float* W_agg    = (const float*)d_in[3];
    const float* b_agg    = (const float*)d_in[4];
    const float* W_lin    = (const float*)d_in[5];  // [2, 512, 256]
    const float* b_lin    = (const float*)d_in[6];  // [2, 256]

    __half* aggb = (__half*)d_out;      // region1: [0, 4.19MB) fp16 agg1 rows
    float*  out  = (float*)d_out;       // final overwrite (post-barrier)

    cudaFuncSetAttribute(final2_kernel,
                         cudaFuncAttributeMaxDynamicSharedMemorySize, F2_SMEM);

    dim3 gblk(32, 16);
    init_owner_kernel<<<(N_NODES + 255) / 256, 256>>>();
    owner_scatter_kernel<<<(BATCH + 255) / 256, 256>>>(node_idx);
    aggb_gemm_kernel<<<BATCH / 64, gblk>>>(feats, W_agg, b_agg, aggb);
    final2_kernel<<<BATCH / 64, gblk, F2_SMEM>>>(
        node_idx, feats, nbd, W_agg, b_agg,
        W_lin, b_lin, W_lin + 512 * 256, b_lin + 256, aggb, out);
}

// round 9
// speedup vs baseline: 2.2792x; 1.2207x over previous
#include <cuda_runtime.h>
#include <cuda_fp16.h>
#include <math.h>

#define N_NODES 50000
#define DEG     16
#define WIDTH   256
#define BATCH   8192
#define EPS     1e-12f

#define LDB  264    // B staging leading dim (halves): 528B rows, conflict-free
#define LDH  264    // H1/nm2 smem leading dim (halves)
#define LDAF 520    // full A-tile leading dim (halves): 1040B rows, conflict-free
#define WH_HALF_OFF (BATCH * WIDTH)   // Wh region starts at this half-offset in d_out

// ---- device globals: ~0.2MB (big scratch lives in d_out) ----
__device__ int      g_owner[N_NODES];
__device__ unsigned g_barCount;
__device__ unsigned g_barPhase;

// ---------------------------------------------------------------------------
// mma helpers
// ---------------------------------------------------------------------------
__device__ __forceinline__ unsigned smem_u32(const void* p) {
    return (unsigned)__cvta_generic_to_shared(p);
}
__device__ __forceinline__ void ldm_x4(unsigned& r0, unsigned& r1, unsigned& r2,
                                       unsigned& r3, unsigned a) {
    asm volatile("ldmatrix.sync.aligned.m8n8.x4.shared.b16 {%0,%1,%2,%3},[%4];"
                 : "=r"(r0), "=r"(r1), "=r"(r2), "=r"(r3) : "r"(a));
}
__device__ __forceinline__ void ldm_x4t(unsigned& r0, unsigned& r1, unsigned& r2,
                                        unsigned& r3, unsigned a) {
    asm volatile("ldmatrix.sync.aligned.m8n8.x4.trans.shared.b16 {%0,%1,%2,%3},[%4];"
                 : "=r"(r0), "=r"(r1), "=r"(r2), "=r"(r3) : "r"(a));
}
__device__ __forceinline__ void mma16816(float* c, unsigned a0, unsigned a1,
                                         unsigned a2, unsigned a3,
                                         unsigned b0, unsigned b1) {
    asm volatile(
        "mma.sync.aligned.m16n8k16.row.col.f32.f16.f16.f32 "
        "{%0,%1,%2,%3},{%4,%5,%6,%7},{%8,%9},{%0,%1,%2,%3};"
        : "+f"(c[0]), "+f"(c[1]), "+f"(c[2]), "+f"(c[3])
        : "r"(a0), "r"(a1), "r"(a2), "r"(a3), "r"(b0), "r"(b1));
}

struct LaneGeom { int aRow, aCol, bRow, bCol; };

// one 32-K chunk of mma: aBase already includes the chunk's K offset (bytes)
__device__ __forceinline__ void mma_chunk(float (*c)[4], unsigned aBase, int lda,
                                          unsigned bBase, int n0, const LaneGeom& lg) {
#pragma unroll
    for (int ks = 0; ks < 2; ++ks) {
        const int k0 = ks * 16;
        unsigned a0, a1, a2, a3;
        ldm_x4(a0, a1, a2, a3,
               aBase + (unsigned)((lg.aRow * lda + k0 + lg.aCol) * 2));
#pragma unroll
        for (int jj = 0; jj < 4; ++jj) {
            unsigned b0, b1, b2, b3;
            ldm_x4t(b0, b1, b2, b3,
                    bBase + (unsigned)(((k0 + lg.bRow) * LDB + n0 + jj * 16 + lg.bCol) * 2));
            mma16816(c[2 * jj],     a0, a1, a2, a3, b0, b1);
            mma16816(c[2 * jj + 1], a0, a1, a2, a3, b2, b3);
        }
    }
}

// async-copy one 32-row fp16 W chunk (16KB) into a B buffer; 2x16B per thread
__device__ __forceinline__ void issue_B(const __half* Wh, int kbase, __half* buf, int tid) {
#pragma unroll
    for (int p = 0; p < 2; ++p) {
        int o = tid + p * 512;
        int kk = o >> 5, seg = o & 31;
        unsigned dst = smem_u32(buf + kk * LDB + seg * 8);
        unsigned long long src =
            (unsigned long long)__cvta_generic_to_global(Wh + (kbase + kk) * 256 + seg * 8);
        asm volatile("cp.async.cg.shared.global [%0],[%1],16;" :: "r"(dst), "l"(src));
    }
    asm volatile("cp.async.commit_group;" ::: "memory");
}

// double-buffered pipelined GEMM over nChunks 32-K chunks.
// A operand: chunk t<8 -> aLo + t*64 bytes; t>=8 -> aHi + (t-8)*64 bytes.
// (pass aHi = aLo + 512 for a single contiguous operand)
__device__ __forceinline__ void gemm_pipe(float (*c)[4], unsigned aLo, unsigned aHi,
                                          int lda, const __half* Wh, int nChunks,
                                          __half* b0, __half* b1, int tid, int n0,
                                          const LaneGeom& lg, bool pre0) {
    if (!pre0) issue_B(Wh, 0, b0, tid);
#pragma unroll 1
    for (int t = 0; t < nChunks; ++t) {
        __half* cur = (t & 1) ? b1 : b0;
        __half* nxt = (t & 1) ? b0 : b1;
        if (t + 1 < nChunks) {
            issue_B(Wh, (t + 1) * 32, nxt, tid);
            asm volatile("cp.async.wait_group 1;" ::: "memory");
        } else {
            asm volatile("cp.async.wait_group 0;" ::: "memory");
        }
        __syncthreads();
        unsigned aB = (t < 8) ? (aLo + (unsigned)(t * 64))
                              : (aHi + (unsigned)((t - 8) * 64));
        mma_chunk(c, aB, lda, smem_u32(cur), n0, lg);
        __syncthreads();
    }
}

// ---------------------------------------------------------------------------
// setup kernels
// ---------------------------------------------------------------------------
__global__ void init_owner_kernel() {
    int i = blockIdx.x * 256 + threadIdx.x;
    if (i < N_NODES) g_owner[i] = -1;
}
__global__ void owner_scatter_kernel(const int* __restrict__ node_idx) {
    int i = blockIdx.x * 256 + threadIdx.x;
    if (i < BATCH) atomicMax(&g_owner[node_idx[i]], i);   // last-wins on dups
}
// weights -> fp16: Wh = [W0 (512x256) | W1 (512x256) | W_agg (256x256)]
__global__ void convert_w_kernel(const float* __restrict__ W_agg,
                                 const float* __restrict__ W_lin,
                                 __half* __restrict__ Wh) {
    int i = blockIdx.x * 256 + threadIdx.x;   // float2 index
    if (i < 131072) {
        float2 v = ((const float2*)W_lin)[i];
        ((__half2*)Wh)[i] = __floats2half2_rn(v.x, v.y);
    } else if (i < 163840) {
        float2 v = ((const float2*)W_agg)[i - 131072];
        ((__half2*)Wh)[i] = __floats2half2_rn(v.x, v.y);
    }
}

// ---------------------------------------------------------------------------
// aggb GEMM (pipelined): aggb[i,:] = relu(feats[i,:] @ W_agg + b) -> fp16
// ---------------------------------------------------------------------------
#define AGGB_SMEM (64*LDH*2 + 2*32*LDB*2 + 256*4)   // 68608

__global__ __launch_bounds__(512, 1)
void aggb_gemm_kernel(const float* __restrict__ A, const __half* __restrict__ Waggh,
                      const float* __restrict__ bias, __half* __restrict__ C) {
    extern __shared__ char smp[];
    __half* Af  = (__half*)smp;            // [64][264]
    __half* b0  = Af + 64 * LDH;           // [32][264]
    __half* b1  = b0 + 32 * LDB;
    float*  s_b = (float*)(b1 + 32 * LDB);

    const int tx = threadIdx.x, wid = threadIdx.y;
    const int tid = wid * 32 + tx;
    const int rowBase = blockIdx.x * 64;
    const int warpM = wid & 3, warpN = wid >> 2;
    const int row0 = warpM * 16, n0 = warpN * 64;
    const int g = tx >> 2, t4 = tx & 3, q = tx >> 3, rl = tx & 7;
    LaneGeom lg = {row0 + (q & 1) * 8 + rl, (q >> 1) * 8, (q & 1) * 8 + rl, (q >> 1) * 8};
    const int lr = tid >> 3, lk4 = tid & 7;

    if (tid < 256) s_b[tid] = __ldg(&bias[tid]);
    issue_B(Waggh, 0, b0, tid);            // overlap with A staging

#pragma unroll
    for (int t = 0; t < 8; ++t) {
        float4 v = *(const float4*)&A[(rowBase + lr) * 256 + t * 32 + lk4 * 4];
        __half2* ad = (__half2*)&Af[lr * LDH + t * 32 + lk4 * 4];
        ad[0] = __floats2half2_rn(v.x, v.y);
        ad[1] = __floats2half2_rn(v.z, v.w);
    }

    float c[8][4];
#pragma unroll
    for (int j = 0; j < 8; ++j)
#pragma unroll
        for (int k = 0; k < 4; ++k) c[j][k] = 0.f;

    unsigned AfA = smem_u32(Af);
    gemm_pipe(c, AfA, AfA + 512, LDH, Waggh, 8, b0, b1, tid, n0, lg, true);

    const int rA = rowBase + row0 + g, rB = rA + 8;
#pragma unroll
    for (int j = 0; j < 8; ++j) {
        int n = n0 + j * 8 + 2 * t4;
        float b0v = s_b[n], b1v = s_b[n + 1];
        *(__half2*)&C[rA * 256 + n] =
            __floats2half2_rn(fmaxf(c[j][0] + b0v, 0.f), fmaxf(c[j][1] + b1v, 0.f));
        *(__half2*)&C[rB * 256 + n] =
            __floats2half2_rn(fmaxf(c[j][2] + b0v, 0.f), fmaxf(c[j][3] + b1v, 0.f));
    }
}

// ---------------------------------------------------------------------------
// H1 tile builder: gather full A tile [64][512] fp16 (H0 | nm1), then
// pipelined K=512 GEMM vs W0h, normalize, write dstH1 (LDH stride, fp16).
// Assumes ssum[]==0 on entry; leaves ssum[]==0.
// ---------------------------------------------------------------------------
__device__ __forceinline__ void compute_h1_tile(
    const float* __restrict__ feats, const __half* __restrict__ aggb,
    const int* __restrict__ oArr, const int* __restrict__ nboArr,
    const float* __restrict__ s_bagg, const float* __restrict__ s_bl0,
    float* __restrict__ ssum, __half* __restrict__ dstH1,
    __half* __restrict__ Afull, __half* __restrict__ b0, __half* __restrict__ b1,
    const __half* __restrict__ W0h,
    int tid, int n0, const LaneGeom& lg, int lrA, int lrB2, int t4) {

    const int lr = tid >> 3, lk4 = tid & 7;
    issue_B(W0h, 0, b0, tid);              // overlap W load with gather

    // H0 half: feats[owner] or zeros
    const int o = oArr[lr];
#pragma unroll
    for (int t = 0; t < 8; ++t) {
        float4 v = make_float4(0.f, 0.f, 0.f, 0.f);
        if (o >= 0) v = *(const float4*)&feats[o * 256 + t * 32 + lk4 * 4];
        __half2* ad = (__half2*)&Afull[lr * LDAF + t * 32 + lk4 * 4];
        ad[0] = __floats2half2_rn(v.x, v.y);
        ad[1] = __floats2half2_rn(v.z, v.w);
    }
    // nm1 half: max over 16 neighbors of fp16 agg1 rows
    const int* nbo = &nboArr[lr * DEG];
#pragma unroll 1
    for (int t = 0; t < 8; ++t) {
        const int col = t * 32 + lk4 * 4;
        float4 rb = make_float4(fmaxf(s_bagg[col + 0], 0.f),
                                fmaxf(s_bagg[col + 1], 0.f),
                                fmaxf(s_bagg[col + 2], 0.f),
                                fmaxf(s_bagg[col + 3], 0.f));
        float4 m = make_float4(-1e30f, -1e30f, -1e30f, -1e30f);
#pragma unroll
        for (int d = 0; d < DEG; ++d) {
            int on = nbo[d];
            float4 w;
            if (on >= 0) {
                const __half2* p = (const __half2*)&aggb[on * 256 + col];
                float2 f01 = __half22float2(__ldg(&p[0]));
                float2 f23 = __half22float2(__ldg(&p[1]));
                w = make_float4(f01.x, f01.y, f23.x, f23.y);
            } else {
                w = rb;
            }
            m.x = fmaxf(m.x, w.x); m.y = fmaxf(m.y, w.y);
            m.z = fmaxf(m.z, w.z); m.w = fmaxf(m.w, w.w);
        }
        __half2* ad = (__half2*)&Afull[lr * LDAF + 256 + col];
        ad[0] = __floats2half2_rn(m.x, m.y);
        ad[1] = __floats2half2_rn(m.z, m.w);
    }

    float c[8][4];
#pragma unroll
    for (int j = 0; j < 8; ++j)
#pragma unroll
        for (int k = 0; k < 4; ++k) c[j][k] = 0.f;

    unsigned AfA = smem_u32(Afull);
    gemm_pipe(c, AfA, AfA + 512, LDAF, W0h, 16, b0, b1, tid, n0, lg, true);

    // epilogue: bias+relu, cross-warpN row-norm, write fp16 (dstH1 may alias Afull)
    float ssA = 0.f, ssB = 0.f;
#pragma unroll
    for (int j = 0; j < 8; ++j) {
        int n = n0 + j * 8 + 2 * t4;
        float b0v = s_bl0[n], b1v = s_bl0[n + 1];
        c[j][0] = fmaxf(c[j][0] + b0v, 0.f);
        c[j][1] = fmaxf(c[j][1] + b1v, 0.f);
        c[j][2] = fmaxf(c[j][2] + b0v, 0.f);
        c[j][3] = fmaxf(c[j][3] + b1v, 0.f);
        ssA = fmaf(c[j][0], c[j][0], fmaf(c[j][1], c[j][1], ssA));
        ssB = fmaf(c[j][2], c[j][2], fmaf(c[j][3], c[j][3], ssB));
    }
    ssA += __shfl_xor_sync(0xffffffffu, ssA, 1);
    ssA += __shfl_xor_sync(0xffffffffu, ssA, 2);
    ssB += __shfl_xor_sync(0xffffffffu, ssB, 1);
    ssB += __shfl_xor_sync(0xffffffffu, ssB, 2);
    if (t4 == 0) { atomicAdd(&ssum[lrA], ssA); atomicAdd(&ssum[lrB2], ssB); }
    __syncthreads();
    float invA = 1.f / fmaxf(sqrtf(ssum[lrA]), EPS);
    float invB = 1.f / fmaxf(sqrtf(ssum[lrB2]), EPS);
    __syncthreads();
    if (tid < 64) ssum[tid] = 0.f;
#pragma unroll
    for (int j = 0; j < 8; ++j) {
        int n = n0 + j * 8 + 2 * t4;
        *(__half2*)&dstH1[lrA * LDH + n]  =
            __floats2half2_rn(c[j][0] * invA, c[j][1] * invA);
        *(__half2*)&dstH1[lrB2 * LDH + n] =
            __floats2half2_rn(c[j][2] * invB, c[j][3] * invB);
    }
    __syncthreads();
}

// ---------------------------------------------------------------------------
// final2: one block per 64 batch rows; fully local recompute.
// ---------------------------------------------------------------------------
#define F2_SMEM (64*LDAF*2 + 2*64*LDH*2 + 2*32*LDB*2 + (256*3+64)*4 + (64*4 + 2*64*DEG)*4)

__global__ __launch_bounds__(512, 1)
void final2_kernel(const int* __restrict__ node_idx, const float* __restrict__ feats,
                   const int* __restrict__ nbd,
                   const float* __restrict__ b_agg, const float* __restrict__ b0v_,
                   const float* __restrict__ b1v_,
                   const __half* __restrict__ W0h, const __half* __restrict__ W1h,
                   const __half* __restrict__ Waggh,
                   const __half* __restrict__ aggb, float* __restrict__ out) {
    extern __shared__ char smp[];
    __half* Afull  = (__half*)smp;                 // [64][520]; reused as h1t [64][264]
    __half* selfH1 = Afull + 64 * LDAF;            // [64][264]
    __half* nm2    = selfH1 + 64 * LDH;            // [64][264]
    __half* b0     = nm2 + 64 * LDH;               // [32][264]
    __half* b1     = b0 + 32 * LDB;                // [32][264]
    float*  s_bagg = (float*)(b1 + 32 * LDB);      // 256
    float*  s_bl0  = s_bagg + 256;
    float*  s_bl1  = s_bl0 + 256;
    float*  ssum   = s_bl1 + 256;                  // 64
    int*    xs     = (int*)(ssum + 64);            // 64
    int*    oS     = xs + 64;
    int*    oT     = oS + 64;
    int*    s_nid  = oT + 64;
    int*    nboS   = s_nid + 64;                   // 1024
    int*    nboT   = nboS + 1024;                  // 1024

    const int tx = threadIdx.x, wid = threadIdx.y;
    const int tid = wid * 32 + tx;
    const int rB = blockIdx.x * 64;
    const int warpM = wid & 3, warpN = wid >> 2;
    const int row0 = warpM * 16, n0 = warpN * 64;
    const int g = tx >> 2, t4 = tx & 3, q = tx >> 3, rl = tx & 7;
    LaneGeom lg = {row0 + (q & 1) * 8 + rl, (q >> 1) * 8, (q & 1) * 8 + rl, (q >> 1) * 8};
    const int lrA = row0 + g, lrB2 = lrA + 8;

    if (tid < 256) {
        s_bagg[tid] = __ldg(&b_agg[tid]);
        s_bl0[tid]  = __ldg(&b0v_[tid]);
        s_bl1[tid]  = __ldg(&b1v_[tid]);
    }
    if (tid < 64) {
        ssum[tid] = 0.f;
        int x = __ldg(&node_idx[rB + tid]);
        xs[tid] = x;
        oS[tid] = g_owner[x];
    }
    __syncthreads();
    for (int e = tid; e < 64 * DEG; e += 512)
        nboS[e] = g_owner[__ldg(&nbd[xs[e >> 4] * DEG + (e & 15)])];
    __syncthreads();

    const unsigned h1tA = smem_u32(Afull);   // h1t lives in Afull region (LDH stride)
    const unsigned selfA = smem_u32(selfH1), nm2A = smem_u32(nm2);

    // ---- self H1 tile ----
    compute_h1_tile(feats, aggb, oS, nboS, s_bagg, s_bl0, ssum, selfH1,
                    Afull, b0, b1, W0h, tid, n0, lg, lrA, lrB2, t4);

    // ---- 16 neighbor tiles: H1 -> agg2 -> group-max into nm2 ----
#pragma unroll 1
    for (int nt = 0; nt < 16; ++nt) {
        if (tid < 64) {
            int il = nt * 4 + (tid >> 4);
            int n = __ldg(&nbd[xs[il] * DEG + (tid & 15)]);
            s_nid[tid] = n;
            oT[tid] = g_owner[n];
        }
        __syncthreads();
        for (int e = tid; e < 64 * DEG; e += 512)
            nboT[e] = g_owner[__ldg(&nbd[s_nid[e >> 4] * DEG + (e & 15)])];
        __syncthreads();

        // H1 of the 64 neighbor nodes -> h1t (in Afull region)
        compute_h1_tile(feats, aggb, oT, nboT, s_bagg, s_bl0, ssum,
                        (__half*)Afull, Afull, b0, b1, W0h,
                        tid, n0, lg, lrA, lrB2, t4);

        // agg2 = relu(h1t @ W_agg + b_agg)
        float c[8][4];
#pragma unroll
        for (int j = 0; j < 8; ++j)
#pragma unroll
            for (int k = 0; k < 4; ++k) c[j][k] = 0.f;
        gemm_pipe(c, h1tA, h1tA + 512, LDH, Waggh, 8, b0, b1, tid, n0, lg, false);

        // bias+relu, max over this warpM group's 16 rows (one batch entry)
#pragma unroll
        for (int j = 0; j < 8; ++j) {
            int n = n0 + j * 8 + 2 * t4;
            float bb0 = s_bagg[n], bb1 = s_bagg[n + 1];
            float a0 = fmaxf(fmaxf(c[j][0] + bb0, 0.f), fmaxf(c[j][2] + bb0, 0.f));
            float a1 = fmaxf(fmaxf(c[j][1] + bb1, 0.f), fmaxf(c[j][3] + bb1, 0.f));
#pragma unroll
            for (int mask = 4; mask <= 16; mask <<= 1) {
                a0 = fmaxf(a0, __shfl_xor_sync(0xffffffffu, a0, mask));
                a1 = fmaxf(a1, __shfl_xor_sync(0xffffffffu, a1, mask));
            }
            *(__half2*)&nm2[(nt * 4 + warpM) * LDH + n] = __floats2half2_rn(a0, a1);
        }
        __syncthreads();
    }

    // ---- final GEMM: [selfH1 | nm2] @ W1, K=512 ----
    float c[8][4];
#pragma unroll
    for (int j = 0; j < 8; ++j)
#pragma unroll
        for (int k = 0; k < 4; ++k) c[j][k] = 0.f;
    gemm_pipe(c, selfA, nm2A, LDH, W1h, 16, b0, b1, tid, n0, lg, false);

    // epilogue: bias+relu+normalize (values stay in registers across barrier)
    float invA, invB;
    {
        float ssA = 0.f, ssB = 0.f;
#pragma unroll
        for (int j = 0; j < 8; ++j) {
            int n = n0 + j * 8 + 2 * t4;
            float bb0 = s_bl1[n], bb1 = s_bl1[n + 1];
            c[j][0] = fmaxf(c[j][0] + bb0, 0.f);
            c[j][1] = fmaxf(c[j][1] + bb1, 0.f);
            c[j][2] = fmaxf(c[j][2] + bb0, 0.f);
            c[j][3] = fmaxf(c[j][3] + bb1, 0.f);
            ssA = fmaf(c[j][0], c[j][0], fmaf(c[j][1], c[j][1], ssA));
            ssB = fmaf(c[j][2], c[j][2], fmaf(c[j][3], c[j][3], ssB));
        }
        ssA += __shfl_xor_sync(0xffffffffu, ssA, 1);
        ssA += __shfl_xor_sync(0xffffffffu, ssA, 2);
        ssB += __shfl_xor_sync(0xffffffffu, ssB, 1);
        ssB += __shfl_xor_sync(0xffffffffu, ssB, 2);
        if (t4 == 0) { atomicAdd(&ssum[lrA], ssA); atomicAdd(&ssum[lrB2], ssB); }
        __syncthreads();
        invA = 1.f / fmaxf(sqrtf(ssum[lrA]), EPS);
        invB = 1.f / fmaxf(sqrtf(ssum[lrB2]), EPS);
    }

    // ---- grid barrier: all d_out reads (aggb/Wh) done before overwrite ----
    __syncthreads();
    if (tid == 0) {
        unsigned phase = atomicAdd(&g_barPhase, 0u);
        unsigned t = atomicAdd(&g_barCount, 1u);
        if (t == gridDim.x - 1) {
            g_barCount = 0u;
            __threadfence();
            atomicAdd(&g_barPhase, 1u);
        } else {
            while (atomicAdd(&g_barPhase, 0u) == phase) { }
        }
    }
    __syncthreads();

    // ---- write out ----
#pragma unroll
    for (int j = 0; j < 8; ++j) {
        int n = n0 + j * 8 + 2 * t4;
        *(float2*)&out[(rB + lrA) * 256 + n] =
            make_float2(c[j][0] * invA, c[j][1] * invA);
        *(float2*)&out[(rB + lrB2) * 256 + n] =
            make_float2(c[j][2] * invB, c[j][3] * invB);
    }
}

// ---------------------------------------------------------------------------
// launch: node_idx, feats, nbd, W_agg, b_agg, W_lin, b_lin  -> out [B,256]
// ---------------------------------------------------------------------------
extern "C" void kernel_launch(void* const* d_in, const int* in_sizes, int n_in,
                              void* d_out, int out_size) {
    const int*   node_idx = (const int*)d_in[0];
    const float* feats    = (const float*)d_in[1];
    const int*   nbd      = (const int*)d_in[2];
    const float* W_agg    = (const float*)d_in[3];
    const float* b_agg    = (const float*)d_in[4];
    const float* W_lin    = (const float*)d_in[5];  // [2, 512, 256]
    const float* b_lin    = (const float*)d_in[6];  // [2, 256]

    __half* aggb = (__half*)d_out;                    // [0, 4.19MB) fp16 agg1
    __half* Wh   = (__half*)d_out + WH_HALF_OFF;      // fp16 weights (640KB)
    const __half* W0h   = Wh;
    const __half* W1h   = Wh + 512 * 256;
    const __half* Waggh = Wh + 2 * 512 * 256;
    float* out = (float*)d_out;                       // overwritten post-barrier

    cudaFuncSetAttribute(aggb_gemm_kernel,
                         cudaFuncAttributeMaxDynamicSharedMemorySize, AGGB_SMEM);
    cudaFuncSetAttribute(final2_kernel,
                         cudaFuncAttributeMaxDynamicSharedMemorySize, F2_SMEM);

    dim3 gblk(32, 16);
    init_owner_kernel<<<(N_NODES + 255) / 256, 256>>>();
    owner_scatter_kernel<<<(BATCH + 255) / 256, 256>>>(node_idx);
    convert_w_kernel<<<640, 256>>>(W_agg, W_lin, Wh);
    aggb_gemm_kernel<<<BATCH / 64, gblk, AGGB_SMEM>>>(feats, Waggh, b_agg, aggb);
    final2_kernel<<<BATCH / 64, gblk, F2_SMEM>>>(
        node_idx, feats, nbd, b_agg, b_lin, b_lin + 256,
        W0h, W1h, Waggh, aggb, out);
}

// round 10
// speedup vs baseline: 2.7087x; 1.1884x over previous
#include <cuda_runtime.h>
#include <cuda_fp16.h>
#include <math.h>

#define N_NODES 50000
#define DEG     16
#define WIDTH   256
#define BATCH   8192
#define EPS     1e-12f

#define LDB  264    // B staging leading dim (halves): 528B rows, conflict-free
#define LDH  264    // A/H1/nm2 smem leading dim (halves)

// ---- device globals: ~0.85MB total ----
__device__ int      g_owner[N_NODES];          // 200KB
__device__ __half   g_Wh[327680];              // 640KB: W0top|W0bot|W1|Wagg (fp16)
__device__ unsigned g_barCount;
__device__ unsigned g_barPhase;

// ---------------------------------------------------------------------------
// mma helpers
// ---------------------------------------------------------------------------
__device__ __forceinline__ unsigned smem_u32(const void* p) {
    return (unsigned)__cvta_generic_to_shared(p);
}
__device__ __forceinline__ void ldm_x4(unsigned& r0, unsigned& r1, unsigned& r2,
                                       unsigned& r3, unsigned a) {
    asm volatile("ldmatrix.sync.aligned.m8n8.x4.shared.b16 {%0,%1,%2,%3},[%4];"
                 : "=r"(r0), "=r"(r1), "=r"(r2), "=r"(r3) : "r"(a));
}
__device__ __forceinline__ void ldm_x4t(unsigned& r0, unsigned& r1, unsigned& r2,
                                        unsigned& r3, unsigned a) {
    asm volatile("ldmatrix.sync.aligned.m8n8.x4.trans.shared.b16 {%0,%1,%2,%3},[%4];"
                 : "=r"(r0), "=r"(r1), "=r"(r2), "=r"(r3) : "r"(a));
}
__device__ __forceinline__ void mma16816(float* c, unsigned a0, unsigned a1,
                                         unsigned a2, unsigned a3,
                                         unsigned b0, unsigned b1) {
    asm volatile(
        "mma.sync.aligned.m16n8k16.row.col.f32.f16.f16.f32 "
        "{%0,%1,%2,%3},{%4,%5,%6,%7},{%8,%9},{%0,%1,%2,%3};"
        : "+f"(c[0]), "+f"(c[1]), "+f"(c[2]), "+f"(c[3])
        : "r"(a0), "r"(a1), "r"(a2), "r"(a3), "r"(b0), "r"(b1));
}

struct LaneGeom { int aRow, aCol, bRow, bCol; };

__device__ __forceinline__ void mma_chunk(float (*c)[4], unsigned aBase, int lda,
                                          unsigned bBase, int n0, const LaneGeom& lg) {
#pragma unroll
    for (int ks = 0; ks < 2; ++ks) {
        const int k0 = ks * 16;
        unsigned a0, a1, a2, a3;
        ldm_x4(a0, a1, a2, a3,
               aBase + (unsigned)((lg.aRow * lda + k0 + lg.aCol) * 2));
#pragma unroll
        for (int jj = 0; jj < 4; ++jj) {
            unsigned b0, b1, b2, b3;
            ldm_x4t(b0, b1, b2, b3,
                    bBase + (unsigned)(((k0 + lg.bRow) * LDB + n0 + jj * 16 + lg.bCol) * 2));
            mma16816(c[2 * jj],     a0, a1, a2, a3, b0, b1);
            mma16816(c[2 * jj + 1], a0, a1, a2, a3, b2, b3);
        }
    }
}

// async-copy one 32-row fp16 W chunk (16KB) into a B buffer
__device__ __forceinline__ void issue_B(const __half* Wh, int kbase, __half* buf, int tid) {
#pragma unroll
    for (int p = 0; p < 2; ++p) {
        int o = tid + p * 512;
        int kk = o >> 5, seg = o & 31;
        unsigned dst = smem_u32(buf + kk * LDB + seg * 8);
        unsigned long long src =
            (unsigned long long)__cvta_generic_to_global(Wh + (kbase + kk) * 256 + seg * 8);
        asm volatile("cp.async.cg.shared.global [%0],[%1],16;" :: "r"(dst), "l"(src));
    }
    asm volatile("cp.async.commit_group;" ::: "memory");
}

// double-buffered pipelined GEMM over nChunks 32-K chunks.
__device__ __forceinline__ void gemm_pipe(float (*c)[4], unsigned aLo, unsigned aHi,
                                          int lda, const __half* Wh, int nChunks,
                                          __half* b0, __half* b1, int tid, int n0,
                                          const LaneGeom& lg, bool pre0) {
    if (!pre0) issue_B(Wh, 0, b0, tid);
#pragma unroll 1
    for (int t = 0; t < nChunks; ++t) {
        __half* cur = (t & 1) ? b1 : b0;
        __half* nxt = (t & 1) ? b0 : b1;
        if (t + 1 < nChunks) {
            issue_B(Wh, (t + 1) * 32, nxt, tid);
            asm volatile("cp.async.wait_group 1;" ::: "memory");
        } else {
            asm volatile("cp.async.wait_group 0;" ::: "memory");
        }
        __syncthreads();
        unsigned aB = (t < 8) ? (aLo + (unsigned)(t * 64))
                              : (aHi + (unsigned)((t - 8) * 64));
        mma_chunk(c, aB, lda, smem_u32(cur), n0, lg);
        __syncthreads();
    }
}

// ---------------------------------------------------------------------------
// setup kernels
// ---------------------------------------------------------------------------
__global__ void init_owner_kernel() {
    int i = blockIdx.x * 256 + threadIdx.x;
    if (i < N_NODES) g_owner[i] = -1;
}
__global__ void owner_scatter_kernel(const int* __restrict__ node_idx) {
    int i = blockIdx.x * 256 + threadIdx.x;
    if (i < BATCH) atomicMax(&g_owner[node_idx[i]], i);   // last-wins on dups
}
// g_Wh = [W0top (256x256) | W0bot (256x256) | W1 (512x256) | Wagg (256x256)]
// (first three are W_lin contiguous; Wagg appended)
__global__ void convert_w_kernel(const float* __restrict__ W_agg,
                                 const float* __restrict__ W_lin) {
    int i = blockIdx.x * 256 + threadIdx.x;   // half2 index
    if (i < 131072) {
        float2 v = ((const float2*)W_lin)[i];
        ((__half2*)g_Wh)[i] = __floats2half2_rn(v.x, v.y);
    } else if (i < 163840) {
        float2 v = ((const float2*)W_agg)[i - 131072];
        ((__half2*)g_Wh)[i] = __floats2half2_rn(v.x, v.y);
    }
}

// ---------------------------------------------------------------------------
// pre GEMM (K=256, pipelined): C[i,:] = act(A[i,:] @ Wh + bias) -> fp16
//   RELU=true  + bias : aggb
//   RELU=false + null : fW0 (plain linear)
// ---------------------------------------------------------------------------
#define PRE_SMEM (64*LDH*2 + 2*32*LDB*2 + 256*4)   // 68608

template <bool RELU>
__global__ __launch_bounds__(512, 1)
void pre_gemm_kernel(const float* __restrict__ A, const __half* __restrict__ Wh,
                     const float* __restrict__ bias, __half* __restrict__ C) {
    extern __shared__ char smp[];
    __half* Af  = (__half*)smp;            // [64][264]
    __half* b0  = Af + 64 * LDH;           // [32][264]
    __half* b1  = b0 + 32 * LDB;
    float*  s_b = (float*)(b1 + 32 * LDB);

    const int tx = threadIdx.x, wid = threadIdx.y;
    const int tid = wid * 32 + tx;
    const int rowBase = blockIdx.x * 64;
    const int warpM = wid & 3, warpN = wid >> 2;
    const int row0 = warpM * 16, n0 = warpN * 64;
    const int g = tx >> 2, t4 = tx & 3, q = tx >> 3, rl = tx & 7;
    LaneGeom lg = {row0 + (q & 1) * 8 + rl, (q >> 1) * 8, (q & 1) * 8 + rl, (q >> 1) * 8};
    const int lr = tid >> 3, lk4 = tid & 7;

    if (tid < 256) s_b[tid] = bias ? __ldg(&bias[tid]) : 0.f;
    issue_B(Wh, 0, b0, tid);               // overlap with A staging

#pragma unroll
    for (int t = 0; t < 8; ++t) {
        float4 v = *(const float4*)&A[(rowBase + lr) * 256 + t * 32 + lk4 * 4];
        __half2* ad = (__half2*)&Af[lr * LDH + t * 32 + lk4 * 4];
        ad[0] = __floats2half2_rn(v.x, v.y);
        ad[1] = __floats2half2_rn(v.z, v.w);
    }

    float c[8][4];
#pragma unroll
    for (int j = 0; j < 8; ++j)
#pragma unroll
        for (int k = 0; k < 4; ++k) c[j][k] = 0.f;

    unsigned AfA = smem_u32(Af);
    gemm_pipe(c, AfA, AfA + 512, LDH, Wh, 8, b0, b1, tid, n0, lg, true);

    const int rA = rowBase + row0 + g, rB = rA + 8;
#pragma unroll
    for (int j = 0; j < 8; ++j) {
        int n = n0 + j * 8 + 2 * t4;
        float b0v = s_b[n], b1v = s_b[n + 1];
        float v0 = c[j][0] + b0v, v1 = c[j][1] + b1v;
        float v2 = c[j][2] + b0v, v3 = c[j][3] + b1v;
        if (RELU) {
            v0 = fmaxf(v0, 0.f); v1 = fmaxf(v1, 0.f);
            v2 = fmaxf(v2, 0.f); v3 = fmaxf(v3, 0.f);
        }
        *(__half2*)&C[rA * 256 + n] = __floats2half2_rn(v0, v1);
        *(__half2*)&C[rB * 256 + n] = __floats2half2_rn(v2, v3);
    }
}

// ---------------------------------------------------------------------------
// H1 tile builder (K=256): gather nm1 [64][256] fp16; init accumulator
// fragments from fW0[owner] (H0 @ W0top, precomputed); GEMM vs W0bot;
// bias+relu+normalize; write dstH1 fp16. Assumes ssum[]==0; leaves 0.
// ---------------------------------------------------------------------------
__device__ __forceinline__ void compute_h1_tile(
    const __half* __restrict__ aggb, const __half* __restrict__ fW0,
    const int* __restrict__ oArr, const int* __restrict__ nboArr,
    const float* __restrict__ s_bagg, const float* __restrict__ s_bl0,
    float* __restrict__ ssum, __half* __restrict__ dstH1,
    __half* __restrict__ Anm1, __half* __restrict__ b0, __half* __restrict__ b1,
    const __half* __restrict__ W0both,
    int tid, int n0, const LaneGeom& lg, int lrA, int lrB2, int t4) {

    const int lr = tid >> 3, lk4 = tid & 7;
    issue_B(W0both, 0, b0, tid);           // overlap W load with gather

    // nm1 gather: max over 16 neighbors of fp16 agg1 rows
    const int* nbo = &nboArr[lr * DEG];
#pragma unroll 1
    for (int t = 0; t < 8; ++t) {
        const int col = t * 32 + lk4 * 4;
        float4 rb = make_float4(fmaxf(s_bagg[col + 0], 0.f),
                                fmaxf(s_bagg[col + 1], 0.f),
                                fmaxf(s_bagg[col + 2], 0.f),
                                fmaxf(s_bagg[col + 3], 0.f));
        float4 m = make_float4(-1e30f, -1e30f, -1e30f, -1e30f);
#pragma unroll
        for (int d = 0; d < DEG; ++d) {
            int on = nbo[d];
            float4 w;
            if (on >= 0) {
                const __half2* p = (const __half2*)&aggb[on * 256 + col];
                float2 f01 = __half22float2(__ldg(&p[0]));
                float2 f23 = __half22float2(__ldg(&p[1]));
                w = make_float4(f01.x, f01.y, f23.x, f23.y);
            } else {
                w = rb;
            }
            m.x = fmaxf(m.x, w.x); m.y = fmaxf(m.y, w.y);
            m.z = fmaxf(m.z, w.z); m.w = fmaxf(m.w, w.w);
        }
        __half2* ad = (__half2*)&Anm1[lr * LDH + col];
        ad[0] = __floats2half2_rn(m.x, m.y);
        ad[1] = __floats2half2_rn(m.z, m.w);
    }

    // init accumulator from fW0[owner] (H0 @ W0top contribution)
    float c[8][4];
    {
        const int oA = oArr[lrA], oB = oArr[lrB2];
#pragma unroll
        for (int j = 0; j < 8; ++j) {
            int n = n0 + j * 8 + 2 * t4;
            if (oA >= 0) {
                __half2 v = __ldg((const __half2*)&fW0[oA * 256 + n]);
                c[j][0] = __half2float(v.x); c[j][1] = __half2float(v.y);
            } else { c[j][0] = 0.f; c[j][1] = 0.f; }
            if (oB >= 0) {
                __half2 v = __ldg((const __half2*)&fW0[oB * 256 + n]);
                c[j][2] = __half2float(v.x); c[j][3] = __half2float(v.y);
            } else { c[j][2] = 0.f; c[j][3] = 0.f; }
        }
    }

    unsigned AnA = smem_u32(Anm1);
    gemm_pipe(c, AnA, AnA + 512, LDH, W0both, 8, b0, b1, tid, n0, lg, true);

    // epilogue: bias+relu, cross-warpN row-norm, write fp16 (dstH1 may alias Anm1)
    float ssA = 0.f, ssB = 0.f;
#pragma unroll
    for (int j = 0; j < 8; ++j) {
        int n = n0 + j * 8 + 2 * t4;
        float b0v = s_bl0[n], b1v = s_bl0[n + 1];
        c[j][0] = fmaxf(c[j][0] + b0v, 0.f);
        c[j][1] = fmaxf(c[j][1] + b1v, 0.f);
        c[j][2] = fmaxf(c[j][2] + b0v, 0.f);
        c[j][3] = fmaxf(c[j][3] + b1v, 0.f);
        ssA = fmaf(c[j][0], c[j][0], fmaf(c[j][1], c[j][1], ssA));
        ssB = fmaf(c[j][2], c[j][2], fmaf(c[j][3], c[j][3], ssB));
    }
    ssA += __shfl_xor_sync(0xffffffffu, ssA, 1);
    ssA += __shfl_xor_sync(0xffffffffu, ssA, 2);
    ssB += __shfl_xor_sync(0xffffffffu, ssB, 1);
    ssB += __shfl_xor_sync(0xffffffffu, ssB, 2);
    if (t4 == 0) { atomicAdd(&ssum[lrA], ssA); atomicAdd(&ssum[lrB2], ssB); }
    __syncthreads();
    float invA = 1.f / fmaxf(sqrtf(ssum[lrA]), EPS);
    float invB = 1.f / fmaxf(sqrtf(ssum[lrB2]), EPS);
    __syncthreads();
    if (tid < 64) ssum[tid] = 0.f;
#pragma unroll
    for (int j = 0; j < 8; ++j) {
        int n = n0 + j * 8 + 2 * t4;
        *(__half2*)&dstH1[lrA * LDH + n]  =
            __floats2half2_rn(c[j][0] * invA, c[j][1] * invA);
        *(__half2*)&dstH1[lrB2 * LDH + n] =
            __floats2half2_rn(c[j][2] * invB, c[j][3] * invB);
    }
    __syncthreads();
}

// ---------------------------------------------------------------------------
// final2: one block per 64 batch rows; fully local recompute (K=256 H1 tiles).
// ---------------------------------------------------------------------------
#define F2_SMEM (3*64*LDH*2 + 2*32*LDB*2 + (256*3+64)*4 + (4*64 + 2*64*DEG)*4)

__global__ __launch_bounds__(512, 1)
void final2_kernel(const int* __restrict__ node_idx, const int* __restrict__ nbd,
                   const float* __restrict__ b_agg, const float* __restrict__ b0v_,
                   const float* __restrict__ b1v_,
                   const __half* __restrict__ aggb, const __half* __restrict__ fW0,
                   float* __restrict__ out) {
    extern __shared__ char smp[];
    __half* Anm1   = (__half*)smp;                 // [64][264]; reused as h1t
    __half* selfH1 = Anm1 + 64 * LDH;              // [64][264]
    __half* nm2    = selfH1 + 64 * LDH;            // [64][264]
    __half* b0     = nm2 + 64 * LDH;               // [32][264]
    __half* b1     = b0 + 32 * LDB;                // [32][264]
    float*  s_bagg = (float*)(b1 + 32 * LDB);      // 256
    float*  s_bl0  = s_bagg + 256;
    float*  s_bl1  = s_bl0 + 256;
    float*  ssum   = s_bl1 + 256;                  // 64
    int*    xs     = (int*)(ssum + 64);            // 64
    int*    oS     = xs + 64;
    int*    oT     = oS + 64;
    int*    s_nid  = oT + 64;
    int*    nboS   = s_nid + 64;                   // 1024
    int*    nboT   = nboS + 1024;                  // 1024

    const int tx = threadIdx.x, wid = threadIdx.y;
    const int tid = wid * 32 + tx;
    const int rB = blockIdx.x * 64;
    const int warpM = wid & 3, warpN = wid >> 2;
    const int row0 = warpM * 16, n0 = warpN * 64;
    const int g = tx >> 2, t4 = tx & 3, q = tx >> 3, rl = tx & 7;
    LaneGeom lg = {row0 + (q & 1) * 8 + rl, (q >> 1) * 8, (q & 1) * 8 + rl, (q >> 1) * 8};
    const int lrA = row0 + g, lrB2 = lrA + 8;

    const __half* W0both = g_Wh + 65536;
    const __half* W1h    = g_Wh + 131072;
    const __half* Waggh  = g_Wh + 262144;

    if (tid < 256) {
        s_bagg[tid] = __ldg(&b_agg[tid]);
        s_bl0[tid]  = __ldg(&b0v_[tid]);
        s_bl1[tid]  = __ldg(&b1v_[tid]);
    }
    if (tid < 64) {
        ssum[tid] = 0.f;
        int x = __ldg(&node_idx[rB + tid]);
        xs[tid] = x;
        oS[tid] = g_owner[x];
    }
    __syncthreads();
    for (int e = tid; e < 64 * DEG; e += 512)
        nboS[e] = g_owner[__ldg(&nbd[xs[e >> 4] * DEG + (e & 15)])];
    __syncthreads();

    const unsigned h1tA = smem_u32(Anm1);
    const unsigned selfA = smem_u32(selfH1), nm2A = smem_u32(nm2);

    // ---- self H1 tile ----
    compute_h1_tile(aggb, fW0, oS, nboS, s_bagg, s_bl0, ssum, selfH1,
                    Anm1, b0, b1, W0both, tid, n0, lg, lrA, lrB2, t4);

    // ---- 16 neighbor tiles: H1 -> agg2 -> group-max into nm2 ----
#pragma unroll 1
    for (int nt = 0; nt < 16; ++nt) {
        if (tid < 64) {
            int il = nt * 4 + (tid >> 4);
            int n = __ldg(&nbd[xs[il] * DEG + (tid & 15)]);
            s_nid[tid] = n;
            oT[tid] = g_owner[n];
        }
        __syncthreads();
        for (int e = tid; e < 64 * DEG; e += 512)
            nboT[e] = g_owner[__ldg(&nbd[s_nid[e >> 4] * DEG + (e & 15)])];
        __syncthreads();

        // H1 of the 64 neighbor nodes -> h1t (reuses Anm1 region)
        compute_h1_tile(aggb, fW0, oT, nboT, s_bagg, s_bl0, ssum,
                        Anm1, Anm1, b0, b1, W0both, tid, n0, lg, lrA, lrB2, t4);

        // agg2 = relu(h1t @ W_agg + b_agg)
        float c[8][4];
#pragma unroll
        for (int j = 0; j < 8; ++j)
#pragma unroll
            for (int k = 0; k < 4; ++k) c[j][k] = 0.f;
        gemm_pipe(c, h1tA, h1tA + 512, LDH, Waggh, 8, b0, b1, tid, n0, lg, false);

        // bias+relu, max over this warpM group's 16 rows (one batch entry)
#pragma unroll
        for (int j = 0; j < 8; ++j) {
            int n = n0 + j * 8 + 2 * t4;
            float bb0 = s_bagg[n], bb1 = s_bagg[n + 1];
            float a0 = fmaxf(fmaxf(c[j][0] + bb0, 0.f), fmaxf(c[j][2] + bb0, 0.f));
            float a1 = fmaxf(fmaxf(c[j][1] + bb1, 0.f), fmaxf(c[j][3] + bb1, 0.f));
#pragma unroll
            for (int mask = 4; mask <= 16; mask <<= 1) {
                a0 = fmaxf(a0, __shfl_xor_sync(0xffffffffu, a0, mask));
                a1 = fmaxf(a1, __shfl_xor_sync(0xffffffffu, a1, mask));
            }
            *(__half2*)&nm2[(nt * 4 + warpM) * LDH + n] = __floats2half2_rn(a0, a1);
        }
        __syncthreads();
    }

    // ---- final GEMM: [selfH1 | nm2] @ W1, K=512 ----
    float c[8][4];
#pragma unroll
    for (int j = 0; j < 8; ++j)
#pragma unroll
        for (int k = 0; k < 4; ++k) c[j][k] = 0.f;
    gemm_pipe(c, selfA, nm2A, LDH, W1h, 16, b0, b1, tid, n0, lg, false);

    // epilogue: bias+relu+normalize (values stay in registers across barrier)
    float invA, invB;
    {
        float ssA = 0.f, ssB = 0.f;
#pragma unroll
        for (int j = 0; j < 8; ++j) {
            int n = n0 + j * 8 + 2 * t4;
            float bb0 = s_bl1[n], bb1 = s_bl1[n + 1];
            c[j][0] = fmaxf(c[j][0] + bb0, 0.f);
            c[j][1] = fmaxf(c[j][1] + bb1, 0.f);
            c[j][2] = fmaxf(c[j][2] + bb0, 0.f);
            c[j][3] = fmaxf(c[j][3] + bb1, 0.f);
            ssA = fmaf(c[j][0], c[j][0], fmaf(c[j][1], c[j][1], ssA));
            ssB = fmaf(c[j][2], c[j][2], fmaf(c[j][3], c[j][3], ssB));
        }
        ssA += __shfl_xor_sync(0xffffffffu, ssA, 1);
        ssA += __shfl_xor_sync(0xffffffffu, ssA, 2);
        ssB += __shfl_xor_sync(0xffffffffu, ssB, 1);
        ssB += __shfl_xor_sync(0xffffffffu, ssB, 2);
        if (t4 == 0) { atomicAdd(&ssum[lrA], ssA); atomicAdd(&ssum[lrB2], ssB); }
        __syncthreads();
        invA = 1.f / fmaxf(sqrtf(ssum[lrA]), EPS);
        invB = 1.f / fmaxf(sqrtf(ssum[lrB2]), EPS);
    }

    // ---- grid barrier: all d_out reads (aggb/fW0) done before overwrite ----
    __syncthreads();
    if (tid == 0) {
        unsigned phase = atomicAdd(&g_barPhase, 0u);
        unsigned t = atomicAdd(&g_barCount, 1u);
        if (t == gridDim.x - 1) {
            g_barCount = 0u;
            __threadfence();
            atomicAdd(&g_barPhase, 1u);
        } else {
            while (atomicAdd(&g_barPhase, 0u) == phase) { }
        }
    }
    __syncthreads();

    // ---- write out ----
#pragma unroll
    for (int j = 0; j < 8; ++j) {
        int n = n0 + j * 8 + 2 * t4;
        *(float2*)&out[(rB + lrA) * 256 + n] =
            make_float2(c[j][0] * invA, c[j][1] * invA);
        *(float2*)&out[(rB + lrB2) * 256 + n] =
            make_float2(c[j][2] * invB, c[j][3] * invB);
    }
}

// ---------------------------------------------------------------------------
// launch: node_idx, feats, nbd, W_agg, b_agg, W_lin, b_lin  -> out [B,256]
// ---------------------------------------------------------------------------
extern "C" void kernel_launch(void* const* d_in, const int* in_sizes, int n_in,
                              void* d_out, int out_size) {
    const int*   node_idx = (const int*)d_in[0];
    const float* feats    = (const float*)d_in[1];
    const int*   nbd      = (const int*)d_in[2];
    const float* W_agg    = (const float*)d_in[3];
    const float* b_agg    = (const float*)d_in[4];
    const float* W_lin    = (const float*)d_in[5];  // [2, 512, 256]
    const float* b_lin    = (const float*)d_in[6];  // [2, 256]

    // d_out: [0, 4.19MB) aggb fp16 | [4.19MB, 8.39MB) fW0 fp16 (exact fit)
    __half* aggb = (__half*)d_out;
    __half* fW0  = (__half*)d_out + BATCH * WIDTH;
    float*  out  = (float*)d_out;                  // overwritten post-barrier

    // device-side fp16 weight pointers (set by convert_w_kernel)
    __half* Wh_dev = nullptr;
    cudaGetSymbolAddress((void**)&Wh_dev, g_Wh);
    const __half* W0toph = Wh_dev;                 // feats @ W0top -> fW0
    const __half* Waggh  = Wh_dev + 262144;

    cudaFuncSetAttribute(pre_gemm_kernel<true>,
                         cudaFuncAttributeMaxDynamicSharedMemorySize, PRE_SMEM);
    cudaFuncSetAttribute(pre_gemm_kernel<false>,
                         cudaFuncAttributeMaxDynamicSharedMemorySize, PRE_SMEM);
    cudaFuncSetAttribute(final2_kernel,
                         cudaFuncAttributeMaxDynamicSharedMemorySize, F2_SMEM);

    dim3 gblk(32, 16);
    init_owner_kernel<<<(N_NODES + 255) / 256, 256>>>();
    owner_scatter_kernel<<<(BATCH + 255) / 256, 256>>>(node_idx);
    convert_w_kernel<<<640, 256>>>(W_agg, W_lin);
    pre_gemm_kernel<true><<<BATCH / 64, gblk, PRE_SMEM>>>(feats, Waggh, b_agg, aggb);
    pre_gemm_kernel<false><<<BATCH / 64, gblk, PRE_SMEM>>>(feats, W0toph, nullptr, fW0);
    final2_kernel<<<BATCH / 64, gblk, F2_SMEM>>>(
        node_idx, nbd, b_agg, b_lin, b_lin + 256, aggb, fW0, out);
}

// round 11
// speedup vs baseline: 3.3110x; 1.2224x over previous
#include <cuda_runtime.h>
#include <cuda_fp16.h>
#include <math.h>

#define N_NODES 50000
#define DEG     16
#define WIDTH   256
#define BATCH   8192
#define EPS     1e-12f

#define LDB  264    // B staging leading dim (halves): 528B rows, conflict-free
#define LDH  264    // A/H1/nm2 smem leading dim (halves)

// ---- device globals: ~0.85MB total ----
__device__ int      g_owner[N_NODES];          // 200KB
__device__ __half   g_Wh[327680];              // 640KB: W0top|W0bot|W1|Wagg (fp16)
__device__ unsigned g_barCount;
__device__ unsigned g_barPhase;

// ---------------------------------------------------------------------------
// mma helpers
// ---------------------------------------------------------------------------
__device__ __forceinline__ unsigned smem_u32(const void* p) {
    return (unsigned)__cvta_generic_to_shared(p);
}
__device__ __forceinline__ void ldm_x4(unsigned& r0, unsigned& r1, unsigned& r2,
                                       unsigned& r3, unsigned a) {
    asm volatile("ldmatrix.sync.aligned.m8n8.x4.shared.b16 {%0,%1,%2,%3},[%4];"
                 : "=r"(r0), "=r"(r1), "=r"(r2), "=r"(r3) : "r"(a));
}
__device__ __forceinline__ void ldm_x4t(unsigned& r0, unsigned& r1, unsigned& r2,
                                        unsigned& r3, unsigned a) {
    asm volatile("ldmatrix.sync.aligned.m8n8.x4.trans.shared.b16 {%0,%1,%2,%3},[%4];"
                 : "=r"(r0), "=r"(r1), "=r"(r2), "=r"(r3) : "r"(a));
}
__device__ __forceinline__ void mma16816(float* c, unsigned a0, unsigned a1,
                                         unsigned a2, unsigned a3,
                                         unsigned b0, unsigned b1) {
    asm volatile(
        "mma.sync.aligned.m16n8k16.row.col.f32.f16.f16.f32 "
        "{%0,%1,%2,%3},{%4,%5,%6,%7},{%8,%9},{%0,%1,%2,%3};"
        : "+f"(c[0]), "+f"(c[1]), "+f"(c[2]), "+f"(c[3])
        : "r"(a0), "r"(a1), "r"(a2), "r"(a3), "r"(b0), "r"(b1));
}

struct LaneGeom { int aRow, aCol, bRow, bCol; };

__device__ __forceinline__ void mma_chunk(float (*c)[4], unsigned aBase, int lda,
                                          unsigned bBase, int n0, const LaneGeom& lg) {
#pragma unroll
    for (int ks = 0; ks < 2; ++ks) {
        const int k0 = ks * 16;
        unsigned a0, a1, a2, a3;
        ldm_x4(a0, a1, a2, a3,
               aBase + (unsigned)((lg.aRow * lda + k0 + lg.aCol) * 2));
#pragma unroll
        for (int jj = 0; jj < 4; ++jj) {
            unsigned b0, b1, b2, b3;
            ldm_x4t(b0, b1, b2, b3,
                    bBase + (unsigned)(((k0 + lg.bRow) * LDB + n0 + jj * 16 + lg.bCol) * 2));
            mma16816(c[2 * jj],     a0, a1, a2, a3, b0, b1);
            mma16816(c[2 * jj + 1], a0, a1, a2, a3, b2, b3);
        }
    }
}

// async-copy one 32-row fp16 W chunk (16KB) into a B buffer
__device__ __forceinline__ void issue_B(const __half* Wh, int kbase, __half* buf, int tid) {
#pragma unroll
    for (int p = 0; p < 2; ++p) {
        int o = tid + p * 512;
        int kk = o >> 5, seg = o & 31;
        unsigned dst = smem_u32(buf + kk * LDB + seg * 8);
        unsigned long long src =
            (unsigned long long)__cvta_generic_to_global(Wh + (kbase + kk) * 256 + seg * 8);
        asm volatile("cp.async.cg.shared.global [%0],[%1],16;" :: "r"(dst), "l"(src));
    }
    asm volatile("cp.async.commit_group;" ::: "memory");
}

// double-buffered pipelined GEMM over nChunks 32-K chunks.
__device__ __forceinline__ void gemm_pipe(float (*c)[4], unsigned aLo, unsigned aHi,
                                          int lda, const __half* Wh, int nChunks,
                                          __half* b0, __half* b1, int tid, int n0,
                                          const LaneGeom& lg, bool pre0) {
    if (!pre0) issue_B(Wh, 0, b0, tid);
#pragma unroll 1
    for (int t = 0; t < nChunks; ++t) {
        __half* cur = (t & 1) ? b1 : b0;
        __half* nxt = (t & 1) ? b0 : b1;
        if (t + 1 < nChunks) {
            issue_B(Wh, (t + 1) * 32, nxt, tid);
            asm volatile("cp.async.wait_group 1;" ::: "memory");
        } else {
            asm volatile("cp.async.wait_group 0;" ::: "memory");
        }
        __syncthreads();
        unsigned aB = (t < 8) ? (aLo + (unsigned)(t * 64))
                              : (aHi + (unsigned)((t - 8) * 64));
        mma_chunk(c, aB, lda, smem_u32(cur), n0, lg);
        __syncthreads();
    }
}

// ---------------------------------------------------------------------------
// setup kernels
// ---------------------------------------------------------------------------
__global__ void init_owner_kernel() {
    int i = blockIdx.x * 256 + threadIdx.x;
    if (i < N_NODES) g_owner[i] = -1;
}
__global__ void owner_scatter_kernel(const int* __restrict__ node_idx) {
    int i = blockIdx.x * 256 + threadIdx.x;
    if (i < BATCH) atomicMax(&g_owner[node_idx[i]], i);   // last-wins on dups
}
// g_Wh = [W0top (256x256) | W0bot (256x256) | W1 (512x256) | Wagg (256x256)]
__global__ void convert_w_kernel(const float* __restrict__ W_agg,
                                 const float* __restrict__ W_lin) {
    int i = blockIdx.x * 256 + threadIdx.x;   // half2 index
    if (i < 131072) {
        float2 v = ((const float2*)W_lin)[i];
        ((__half2*)g_Wh)[i] = __floats2half2_rn(v.x, v.y);
    } else if (i < 163840) {
        float2 v = ((const float2*)W_agg)[i - 131072];
        ((__half2*)g_Wh)[i] = __floats2half2_rn(v.x, v.y);
    }
}

// ---------------------------------------------------------------------------
// merged pre GEMM (K=256, pipelined): stage feats tile once, then
//   aggb = relu(feats @ Wagg + b_agg)   (fp16)
//   fW0  = feats @ W0top                (fp16, no bias/relu)
// ---------------------------------------------------------------------------
#define PRE_SMEM (64*LDH*2 + 2*32*LDB*2 + 256*4)   // 68608

__global__ __launch_bounds__(512, 1)
void pre_gemm_kernel(const float* __restrict__ A, const float* __restrict__ bias_agg,
                     __half* __restrict__ aggb, __half* __restrict__ fW0) {
    extern __shared__ char smp[];
    __half* Af  = (__half*)smp;            // [64][264]
    __half* b0  = Af + 64 * LDH;           // [32][264]
    __half* b1  = b0 + 32 * LDB;
    float*  s_b = (float*)(b1 + 32 * LDB);

    const int tx = threadIdx.x, wid = threadIdx.y;
    const int tid = wid * 32 + tx;
    const int rowBase = blockIdx.x * 64;
    const int warpM = wid & 3, warpN = wid >> 2;
    const int row0 = warpM * 16, n0 = warpN * 64;
    const int g = tx >> 2, t4 = tx & 3, q = tx >> 3, rl = tx & 7;
    LaneGeom lg = {row0 + (q & 1) * 8 + rl, (q >> 1) * 8, (q & 1) * 8 + rl, (q >> 1) * 8};
    const int lr = tid >> 3, lk4 = tid & 7;

    if (tid < 256) s_b[tid] = __ldg(&bias_agg[tid]);
    issue_B(g_Wh + 262144, 0, b0, tid);    // Wagg chunk 0, overlaps A staging

#pragma unroll
    for (int t = 0; t < 8; ++t) {
        float4 v = *(const float4*)&A[(rowBase + lr) * 256 + t * 32 + lk4 * 4];
        __half2* ad = (__half2*)&Af[lr * LDH + t * 32 + lk4 * 4];
        ad[0] = __floats2half2_rn(v.x, v.y);
        ad[1] = __floats2half2_rn(v.z, v.w);
    }

    const unsigned AfA = smem_u32(Af);
    const int rA = rowBase + row0 + g, rB = rA + 8;

    // ---- GEMM 1: aggb = relu(feats @ Wagg + b_agg) ----
    float c[8][4];
#pragma unroll
    for (int j = 0; j < 8; ++j)
#pragma unroll
        for (int k = 0; k < 4; ++k) c[j][k] = 0.f;
    gemm_pipe(c, AfA, AfA + 512, LDH, g_Wh + 262144, 8, b0, b1, tid, n0, lg, true);
#pragma unroll
    for (int j = 0; j < 8; ++j) {
        int n = n0 + j * 8 + 2 * t4;
        float b0v = s_b[n], b1v = s_b[n + 1];
        *(__half2*)&aggb[rA * 256 + n] =
            __floats2half2_rn(fmaxf(c[j][0] + b0v, 0.f), fmaxf(c[j][1] + b1v, 0.f));
        *(__half2*)&aggb[rB * 256 + n] =
            __floats2half2_rn(fmaxf(c[j][2] + b0v, 0.f), fmaxf(c[j][3] + b1v, 0.f));
    }

    // ---- GEMM 2: fW0 = feats @ W0top ----
#pragma unroll
    for (int j = 0; j < 8; ++j)
#pragma unroll
        for (int k = 0; k < 4; ++k) c[j][k] = 0.f;
    gemm_pipe(c, AfA, AfA + 512, LDH, g_Wh, 8, b0, b1, tid, n0, lg, false);
#pragma unroll
    for (int j = 0; j < 8; ++j) {
        int n = n0 + j * 8 + 2 * t4;
        *(__half2*)&fW0[rA * 256 + n] = __floats2half2_rn(c[j][0], c[j][1]);
        *(__half2*)&fW0[rB * 256 + n] = __floats2half2_rn(c[j][2], c[j][3]);
    }
}

// ---------------------------------------------------------------------------
// H1 tile builder (K=256): vectorized fp16 nm1 gather (uint4 + __hmax2);
// accumulator initialized from fW0[owner]; GEMM vs W0bot; bias+relu+normalize.
// Assumes ssum[]==0 on entry; leaves 0.
// ---------------------------------------------------------------------------
__device__ __forceinline__ void compute_h1_tile(
    const __half* __restrict__ aggb, const __half* __restrict__ fW0,
    const int* __restrict__ oArr, const int* __restrict__ nboArr,
    const __half* __restrict__ s_rbh, const float* __restrict__ s_bl0,
    float* __restrict__ ssum, __half* __restrict__ dstH1,
    __half* __restrict__ Anm1, __half* __restrict__ b0, __half* __restrict__ b1,
    const __half* __restrict__ W0both,
    int tid, int n0, const LaneGeom& lg, int lrA, int lrB2, int t4) {

    const int lr = tid >> 3, lk4 = tid & 7;
    issue_B(W0both, 0, b0, tid);           // overlap W load with gather

    // nm1 gather: 16B loads, fp16 max, direct fp16 store into A tile
    const int* nbo = &nboArr[lr * DEG];
#pragma unroll 1
    for (int t = 0; t < 4; ++t) {
        const int colh = t * 64 + lk4 * 8;         // half offset within row
        uint4 rbv = *(const uint4*)&s_rbh[colh];
        int on0 = nbo[0];
        uint4 w0 = (on0 >= 0) ? __ldg((const uint4*)&aggb[on0 * 256 + colh]) : rbv;
        __half2 m0 = *(__half2*)&w0.x, m1 = *(__half2*)&w0.y;
        __half2 m2 = *(__half2*)&w0.z, m3 = *(__half2*)&w0.w;
#pragma unroll
        for (int d = 1; d < DEG; ++d) {
            int on = nbo[d];
            uint4 w = (on >= 0) ? __ldg((const uint4*)&aggb[on * 256 + colh]) : rbv;
            m0 = __hmax2(m0, *(__half2*)&w.x);
            m1 = __hmax2(m1, *(__half2*)&w.y);
            m2 = __hmax2(m2, *(__half2*)&w.z);
            m3 = __hmax2(m3, *(__half2*)&w.w);
        }
        uint4 mv;
        mv.x = *(unsigned*)&m0; mv.y = *(unsigned*)&m1;
        mv.z = *(unsigned*)&m2; mv.w = *(unsigned*)&m3;
        *(uint4*)&Anm1[lr * LDH + colh] = mv;
    }

    // init accumulator from fW0[owner] (H0 @ W0top contribution)
    float c[8][4];
    {
        const int oA = oArr[lrA], oB = oArr[lrB2];
#pragma unroll
        for (int j = 0; j < 8; ++j) {
            int n = n0 + j * 8 + 2 * t4;
            if (oA >= 0) {
                __half2 v = __ldg((const __half2*)&fW0[oA * 256 + n]);
                c[j][0] = __half2float(v.x); c[j][1] = __half2float(v.y);
            } else { c[j][0] = 0.f; c[j][1] = 0.f; }
            if (oB >= 0) {
                __half2 v = __ldg((const __half2*)&fW0[oB * 256 + n]);
                c[j][2] = __half2float(v.x); c[j][3] = __half2float(v.y);
            } else { c[j][2] = 0.f; c[j][3] = 0.f; }
        }
    }

    unsigned AnA = smem_u32(Anm1);
    gemm_pipe(c, AnA, AnA + 512, LDH, W0both, 8, b0, b1, tid, n0, lg, true);

    // epilogue: bias+relu, cross-warpN row-norm, write fp16 (dstH1 may alias Anm1)
    float ssA = 0.f, ssB = 0.f;
#pragma unroll
    for (int j = 0; j < 8; ++j) {
        int n = n0 + j * 8 + 2 * t4;
        float b0v = s_bl0[n], b1v = s_bl0[n + 1];
        c[j][0] = fmaxf(c[j][0] + b0v, 0.f);
        c[j][1] = fmaxf(c[j][1] + b1v, 0.f);
        c[j][2] = fmaxf(c[j][2] + b0v, 0.f);
        c[j][3] = fmaxf(c[j][3] + b1v, 0.f);
        ssA = fmaf(c[j][0], c[j][0], fmaf(c[j][1], c[j][1], ssA));
        ssB = fmaf(c[j][2], c[j][2], fmaf(c[j][3], c[j][3], ssB));
    }
    ssA += __shfl_xor_sync(0xffffffffu, ssA, 1);
    ssA += __shfl_xor_sync(0xffffffffu, ssA, 2);
    ssB += __shfl_xor_sync(0xffffffffu, ssB, 1);
    ssB += __shfl_xor_sync(0xffffffffu, ssB, 2);
    if (t4 == 0) { atomicAdd(&ssum[lrA], ssA); atomicAdd(&ssum[lrB2], ssB); }
    __syncthreads();
    float invA = 1.f / fmaxf(sqrtf(ssum[lrA]), EPS);
    float invB = 1.f / fmaxf(sqrtf(ssum[lrB2]), EPS);
    __syncthreads();
    if (tid < 64) ssum[tid] = 0.f;
#pragma unroll
    for (int j = 0; j < 8; ++j) {
        int n = n0 + j * 8 + 2 * t4;
        *(__half2*)&dstH1[lrA * LDH + n]  =
            __floats2half2_rn(c[j][0] * invA, c[j][1] * invA);
        *(__half2*)&dstH1[lrB2 * LDH + n] =
            __floats2half2_rn(c[j][2] * invB, c[j][3] * invB);
    }
    __syncthreads();
}

// ---------------------------------------------------------------------------
// final2: one block per 64 batch rows; fully local recompute (K=256 H1 tiles).
// ---------------------------------------------------------------------------
#define F2_SMEM (3*64*LDH*2 + 2*32*LDB*2 + (256*3+64)*4 + 256*2 + (4*64 + 2*64*DEG)*4)

__global__ __launch_bounds__(512, 1)
void final2_kernel(const int* __restrict__ node_idx, const int* __restrict__ nbd,
                   const float* __restrict__ b_agg, const float* __restrict__ b0v_,
                   const float* __restrict__ b1v_,
                   const __half* __restrict__ aggb, const __half* __restrict__ fW0,
                   float* __restrict__ out) {
    extern __shared__ char smp[];
    __half* Anm1   = (__half*)smp;                 // [64][264]; reused as h1t
    __half* selfH1 = Anm1 + 64 * LDH;              // [64][264]
    __half* nm2    = selfH1 + 64 * LDH;            // [64][264]
    __half* b0     = nm2 + 64 * LDH;               // [32][264]
    __half* b1     = b0 + 32 * LDB;                // [32][264]
    float*  s_bagg = (float*)(b1 + 32 * LDB);      // 256
    float*  s_bl0  = s_bagg + 256;
    float*  s_bl1  = s_bl0 + 256;
    float*  ssum   = s_bl1 + 256;                  // 64
    __half* s_rbh  = (__half*)(ssum + 64);         // 256 halves: relu(b_agg) fp16
    int*    xs     = (int*)(s_rbh + 256);          // 64
    int*    oS     = xs + 64;
    int*    oT     = oS + 64;
    int*    s_nid  = oT + 64;
    int*    nboS   = s_nid + 64;                   // 1024
    int*    nboT   = nboS + 1024;                  // 1024

    const int tx = threadIdx.x, wid = threadIdx.y;
    const int tid = wid * 32 + tx;
    const int rB = blockIdx.x * 64;
    const int warpM = wid & 3, warpN = wid >> 2;
    const int row0 = warpM * 16, n0 = warpN * 64;
    const int g = tx >> 2, t4 = tx & 3, q = tx >> 3, rl = tx & 7;
    LaneGeom lg = {row0 + (q & 1) * 8 + rl, (q >> 1) * 8, (q & 1) * 8 + rl, (q >> 1) * 8};
    const int lrA = row0 + g, lrB2 = lrA + 8;

    const __half* W0both = g_Wh + 65536;
    const __half* W1h    = g_Wh + 131072;
    const __half* Waggh  = g_Wh + 262144;
    (void)Waggh;

    if (tid < 256) {
        float ba = __ldg(&b_agg[tid]);
        s_bagg[tid] = ba;
        s_rbh[tid]  = __float2half_rn(fmaxf(ba, 0.f));
        s_bl0[tid]  = __ldg(&b0v_[tid]);
        s_bl1[tid]  = __ldg(&b1v_[tid]);
    }
    if (tid < 64) {
        ssum[tid] = 0.f;
        int x = __ldg(&node_idx[rB + tid]);
        xs[tid] = x;
        oS[tid] = g_owner[x];
    }
    __syncthreads();
    for (int e = tid; e < 64 * DEG; e += 512)
        nboS[e] = g_owner[__ldg(&nbd[xs[e >> 4] * DEG + (e & 15)])];
    __syncthreads();

    const unsigned h1tA = smem_u32(Anm1);
    const unsigned selfA = smem_u32(selfH1), nm2A = smem_u32(nm2);

    // ---- self H1 tile ----
    compute_h1_tile(aggb, fW0, oS, nboS, s_rbh, s_bl0, ssum, selfH1,
                    Anm1, b0, b1, W0both, tid, n0, lg, lrA, lrB2, t4);

    // ---- 16 neighbor tiles: H1 -> agg2 -> group-max into nm2 ----
#pragma unroll 1
    for (int nt = 0; nt < 16; ++nt) {
        if (tid < 64) {
            int il = nt * 4 + (tid >> 4);
            int n = __ldg(&nbd[xs[il] * DEG + (tid & 15)]);
            s_nid[tid] = n;
            oT[tid] = g_owner[n];
        }
        __syncthreads();
        for (int e = tid; e < 64 * DEG; e += 512)
            nboT[e] = g_owner[__ldg(&nbd[s_nid[e >> 4] * DEG + (e & 15)])];
        __syncthreads();

        // H1 of the 64 neighbor nodes -> h1t (reuses Anm1 region)
        compute_h1_tile(aggb, fW0, oT, nboT, s_rbh, s_bl0, ssum,
                        Anm1, Anm1, b0, b1, W0both, tid, n0, lg, lrA, lrB2, t4);

        // agg2 = relu(h1t @ W_agg + b_agg)
        float c[8][4];
#pragma unroll
        for (int j = 0; j < 8; ++j)
#pragma unroll
            for (int k = 0; k < 4; ++k) c[j][k] = 0.f;
        gemm_pipe(c, h1tA, h1tA + 512, LDH, g_Wh + 262144, 8, b0, b1, tid, n0, lg, false);

        // bias+relu, max over this warpM group's 16 rows (one batch entry)
#pragma unroll
        for (int j = 0; j < 8; ++j) {
            int n = n0 + j * 8 + 2 * t4;
            float bb0 = s_bagg[n], bb1 = s_bagg[n + 1];
            float a0 = fmaxf(fmaxf(c[j][0] + bb0, 0.f), fmaxf(c[j][2] + bb0, 0.f));
            float a1 = fmaxf(fmaxf(c[j][1] + bb1, 0.f), fmaxf(c[j][3] + bb1, 0.f));
#pragma unroll
            for (int mask = 4; mask <= 16; mask <<= 1) {
                a0 = fmaxf(a0, __shfl_xor_sync(0xffffffffu, a0, mask));
                a1 = fmaxf(a1, __shfl_xor_sync(0xffffffffu, a1, mask));
            }
            *(__half2*)&nm2[(nt * 4 + warpM) * LDH + n] = __floats2half2_rn(a0, a1);
        }
        __syncthreads();
    }

    // ---- final GEMM: [selfH1 | nm2] @ W1, K=512 ----
    float c[8][4];
#pragma unroll
    for (int j = 0; j < 8; ++j)
#pragma unroll
        for (int k = 0; k < 4; ++k) c[j][k] = 0.f;
    gemm_pipe(c, selfA, nm2A, LDH, W1h, 16, b0, b1, tid, n0, lg, false);

    // epilogue: bias+relu+normalize (values stay in registers across barrier)
    float invA, invB;
    {
        float ssA = 0.f, ssB = 0.f;
#pragma unroll
        for (int j = 0; j < 8; ++j) {
            int n = n0 + j * 8 + 2 * t4;
            float bb0 = s_bl1[n], bb1 = s_bl1[n + 1];
            c[j][0] = fmaxf(c[j][0] + bb0, 0.f);
            c[j][1] = fmaxf(c[j][1] + bb1, 0.f);
            c[j][2] = fmaxf(c[j][2] + bb0, 0.f);
            c[j][3] = fmaxf(c[j][3] + bb1, 0.f);
            ssA = fmaf(c[j][0], c[j][0], fmaf(c[j][1], c[j][1], ssA));
            ssB = fmaf(c[j][2], c[j][2], fmaf(c[j][3], c[j][3], ssB));
        }
        ssA += __shfl_xor_sync(0xffffffffu, ssA, 1);
        ssA += __shfl_xor_sync(0xffffffffu, ssA, 2);
        ssB += __shfl_xor_sync(0xffffffffu, ssB, 1);
        ssB += __shfl_xor_sync(0xffffffffu, ssB, 2);
        if (t4 == 0) { atomicAdd(&ssum[lrA], ssA); atomicAdd(&ssum[lrB2], ssB); }
        __syncthreads();
        invA = 1.f / fmaxf(sqrtf(ssum[lrA]), EPS);
        invB = 1.f / fmaxf(sqrtf(ssum[lrB2]), EPS);
    }

    // ---- grid barrier: all d_out reads (aggb/fW0) done before overwrite ----
    __syncthreads();
    if (tid == 0) {
        unsigned phase = atomicAdd(&g_barPhase, 0u);
        unsigned t = atomicAdd(&g_barCount, 1u);
        if (t == gridDim.x - 1) {
            g_barCount = 0u;
            __threadfence();
            atomicAdd(&g_barPhase, 1u);
        } else {
            while (atomicAdd(&g_barPhase, 0u) == phase) { }
        }
    }
    __syncthreads();

    // ---- write out ----
#pragma unroll
    for (int j = 0; j < 8; ++j) {
        int n = n0 + j * 8 + 2 * t4;
        *(float2*)&out[(rB + lrA) * 256 + n] =
            make_float2(c[j][0] * invA, c[j][1] * invA);
        *(float2*)&out[(rB + lrB2) * 256 + n] =
            make_float2(c[j][2] * invB, c[j][3] * invB);
    }
}

// ---------------------------------------------------------------------------
// launch: node_idx, feats, nbd, W_agg, b_agg, W_lin, b_lin  -> out [B,256]
// ---------------------------------------------------------------------------
extern "C" void kernel_launch(void* const* d_in, const int* in_sizes, int n_in,
                              void* d_out, int out_size) {
    const int*   node_idx = (const int*)d_in[0];
    const float* feats    = (const float*)d_in[1];
    const int*   nbd      = (const int*)d_in[2];
    const float* W_agg    = (const float*)d_in[3];
    const float* b_agg    = (const float*)d_in[4];
    const float* W_lin    = (const float*)d_in[5];  // [2, 512, 256]
    const float* b_lin    = (const float*)d_in[6];  // [2, 256]

    // d_out: [0, 4.19MB) aggb fp16 | [4.19MB, 8.39MB) fW0 fp16 (exact fit)
    __half* aggb = (__half*)d_out;
    __half* fW0  = (__half*)d_out + BATCH * WIDTH;
    float*  out  = (float*)d_out;                  // overwritten post-barrier

    cudaFuncSetAttribute(pre_gemm_kernel,
                         cudaFuncAttributeMaxDynamicSharedMemorySize, PRE_SMEM);
    cudaFuncSetAttribute(final2_kernel,
                         cudaFuncAttributeMaxDynamicSharedMemorySize, F2_SMEM);

    dim3 gblk(32, 16);
    init_owner_kernel<<<(N_NODES + 255) / 256, 256>>>();
    owner_scatter_kernel<<<(BATCH + 255) / 256, 256>>>(node_idx);
    convert_w_kernel<<<640, 256>>>(W_agg, W_lin);
    pre_gemm_kernel<<<BATCH / 64, gblk, PRE_SMEM>>>(feats, b_agg, aggb, fW0);
    final2_kernel<<<BATCH / 64, gblk, F2_SMEM>>>(
        node_idx, nbd, b_agg, b_lin, b_lin + 256, aggb, fW0, out);
}